// round 1
// baseline (speedup 1.0000x reference)
#include <cuda_runtime.h>

// ---------------------------------------------------------------------------
// GeneInteractionDango fused kernel (fp32 baseline)
//
// One block handles GPB=32 groups (96 tokens). All per-token state lives in
// dynamic shared memory (4 buffers of [96][132] floats). The 9 projections
// (static Ws + 2 layers x {Wq,Wk,Wv,Wo}) are computed as small smem-resident
// GEMMs with weights streamed from global (L2-cached: every block reads the
// same 576KB of weights). Attention is a 3-token exclude-self softmax done
// per (group, head) by one thread. Final: score_t = ((dyn-static)^2) @ Wp + bp,
// out_g = mean over the 3 tokens of the group.
// ---------------------------------------------------------------------------

#define GROUPS   131072
#define SEQ      3
#define H        128
#define NH       4
#define HD       32
#define NLAYERS  2
#define GPB      32
#define TPB      (GPB * SEQ)      // 96 tokens per block
#define RS       132              // padded row stride (floats) to dodge bank conflicts
#define NTHREADS 256

// mode: 0 = plain bias, 1 = relu(., + b), 2 = residual: Y += beta*(acc + b)
template <int MODE>
__device__ __forceinline__ void gemm_tile(const float* __restrict__ Xin,
                                          const float* __restrict__ W,
                                          const float* __restrict__ b,
                                          float* __restrict__ Yout,
                                          int tid, float betaVal)
{
    const int tx = tid & 15;       // j-tile: 16 tiles of 8 outputs
    const int ty = tid >> 4;       // t-tile: 16 tiles of 6 tokens

    float acc[6][8];
#pragma unroll
    for (int tt = 0; tt < 6; tt++)
#pragma unroll
        for (int jj = 0; jj < 8; jj++) acc[tt][jj] = 0.0f;

    const float* wcol = W + tx * 8;
    const float* xbase = Xin + (ty * 6) * RS;

#pragma unroll 4
    for (int k = 0; k < H; k++) {
        float4 w0 = __ldg((const float4*)(wcol + (size_t)k * H));
        float4 w1 = __ldg((const float4*)(wcol + (size_t)k * H + 4));
#pragma unroll
        for (int tt = 0; tt < 6; tt++) {
            float xv = xbase[tt * RS + k];
            acc[tt][0] += xv * w0.x;
            acc[tt][1] += xv * w0.y;
            acc[tt][2] += xv * w0.z;
            acc[tt][3] += xv * w0.w;
            acc[tt][4] += xv * w1.x;
            acc[tt][5] += xv * w1.y;
            acc[tt][6] += xv * w1.z;
            acc[tt][7] += xv * w1.w;
        }
    }

    float bb[8];
#pragma unroll
    for (int jj = 0; jj < 8; jj++) bb[jj] = __ldg(b + tx * 8 + jj);

#pragma unroll
    for (int tt = 0; tt < 6; tt++) {
        float* yrow = Yout + (ty * 6 + tt) * RS + tx * 8;
#pragma unroll
        for (int jj = 0; jj < 8; jj++) {
            float v = acc[tt][jj] + bb[jj];
            if (MODE == 0) {
                yrow[jj] = v;
            } else if (MODE == 1) {
                yrow[jj] = fmaxf(v, 0.0f);
            } else {
                yrow[jj] += betaVal * v;
            }
        }
    }
}

__global__ __launch_bounds__(NTHREADS, 1)
void dango_fused_kernel(const float* __restrict__ X0,
                        const float* __restrict__ Ws, const float* __restrict__ bs,
                        const float* __restrict__ Wq, const float* __restrict__ bq,
                        const float* __restrict__ Wk, const float* __restrict__ bk,
                        const float* __restrict__ Wv, const float* __restrict__ bv,
                        const float* __restrict__ Wo, const float* __restrict__ bo,
                        const float* __restrict__ beta,
                        const float* __restrict__ Wp, const float* __restrict__ bp,
                        float* __restrict__ out)
{
    extern __shared__ float sm[];
    float* Xs  = sm;                    // [96][132] current dyn state
    float* Qs  = Xs + TPB * RS;         // [96][132] Q / attention output
    float* Ks  = Qs + TPB * RS;         // [96][132] K / reloaded X0
    float* Vs  = Ks + TPB * RS;         // [96][132] V / static embedding
    float* sWp = Vs + TPB * RS;         // [128]
    float* sSc = sWp + H;               // [96] per-token scores

    const int tid = threadIdx.x;
    const int g0  = blockIdx.x * GPB;
    const size_t base = (size_t)g0 * SEQ * H;

    // ---- load X tile into Xs (padded rows) ----
    for (int idx = tid; idx < TPB * (H / 4); idx += NTHREADS) {
        int row = idx >> 5;        // /32 float4 per row
        int c4  = idx & 31;
        float4 v = __ldg((const float4*)(X0 + base + (size_t)row * H + c4 * 4));
        float* dst = Xs + row * RS + c4 * 4;
        dst[0] = v.x; dst[1] = v.y; dst[2] = v.z; dst[3] = v.w;
    }
    if (tid < H) sWp[tid] = __ldg(Wp + tid);
    __syncthreads();

    // ---- attention layers ----
    for (int l = 0; l < NLAYERS; l++) {
        const float* wq = Wq + (size_t)l * H * H;
        const float* wk = Wk + (size_t)l * H * H;
        const float* wv = Wv + (size_t)l * H * H;
        const float* wo = Wo + (size_t)l * H * H;

        gemm_tile<0>(Xs, wq, bq + l * H, Qs, tid, 0.0f);
        gemm_tile<0>(Xs, wk, bk + l * H, Ks, tid, 0.0f);
        gemm_tile<0>(Xs, wv, bv + l * H, Vs, tid, 0.0f);
        __syncthreads();

        // exclude-self softmax attention, one thread per (group, head).
        if (tid < GPB * NH) {
            const int g = tid >> 2;
            const int h = tid & 3;
            const int rbase = g * SEQ;
            const int ho = h * HD;
            const float inv = 0.17677669529663687f;   // 1/sqrt(32)
#pragma unroll
            for (int qi = 0; qi < SEQ; qi++) {
                const int k0 = (qi == 0) ? 1 : 0;
                const int k1 = (qi == 2) ? 1 : 2;
                float* qrow = Qs + (rbase + qi) * RS + ho;
                const float* k0r = Ks + (rbase + k0) * RS + ho;
                const float* k1r = Ks + (rbase + k1) * RS + ho;
                float s0 = 0.0f, s1 = 0.0f;
#pragma unroll
                for (int d = 0; d < HD; d++) {
                    float q = qrow[d];
                    s0 += q * k0r[d];
                    s1 += q * k1r[d];
                }
                s0 *= inv; s1 *= inv;
                float m  = fmaxf(s0, s1);
                float e0 = expf(s0 - m), e1 = expf(s1 - m);
                float r  = 1.0f / (e0 + e1);
                float w0 = e0 * r, w1 = e1 * r;
                const float* v0 = Vs + (rbase + k0) * RS + ho;
                const float* v1 = Vs + (rbase + k1) * RS + ho;
#pragma unroll
                for (int d = 0; d < HD; d++)
                    qrow[d] = w0 * v0[d] + w1 * v1[d];   // safe: row qi's Q already consumed
            }
        }
        __syncthreads();

        // Xs += beta[l] * (O @ Wo + bo)
        gemm_tile<2>(Qs, wo, bo + l * H, Xs, tid, __ldg(beta + l));
        __syncthreads();
    }

    // ---- static path: reload X0, static = relu(X0 @ Ws + bs) into Vs ----
    for (int idx = tid; idx < TPB * (H / 4); idx += NTHREADS) {
        int row = idx >> 5;
        int c4  = idx & 31;
        float4 v = __ldg((const float4*)(X0 + base + (size_t)row * H + c4 * 4));
        float* dst = Ks + row * RS + c4 * 4;
        dst[0] = v.x; dst[1] = v.y; dst[2] = v.z; dst[3] = v.w;
    }
    __syncthreads();
    gemm_tile<1>(Ks, Ws, bs, Vs, tid, 0.0f);
    __syncthreads();

    // ---- per-token score: ((dyn - static)^2) @ Wp + bp ----
    if (tid < TPB) {
        const float* drow = Xs + tid * RS;
        const float* srow = Vs + tid * RS;
        float s = 0.0f;
#pragma unroll 8
        for (int j = 0; j < H; j++) {
            float d = drow[j] - srow[j];
            s += d * d * sWp[j];
        }
        sSc[tid] = s + __ldg(bp);
    }
    __syncthreads();

    // ---- group mean (count is always 3) ----
    if (tid < GPB) {
        float v = (sSc[tid * 3] + sSc[tid * 3 + 1] + sSc[tid * 3 + 2]) * (1.0f / 3.0f);
        out[g0 + tid] = v;
    }
}

extern "C" void kernel_launch(void* const* d_in, const int* in_sizes, int n_in,
                              void* d_out, int out_size)
{
    const float* X0  = (const float*)d_in[0];
    // d_in[1] = batch (int64) — implicit: repeat(arange(G), 3)
    const float* Ws  = (const float*)d_in[2];
    const float* bs  = (const float*)d_in[3];
    const float* Wq  = (const float*)d_in[4];
    const float* bq  = (const float*)d_in[5];
    const float* Wk  = (const float*)d_in[6];
    const float* bk  = (const float*)d_in[7];
    const float* Wv  = (const float*)d_in[8];
    const float* bv  = (const float*)d_in[9];
    const float* Wo  = (const float*)d_in[10];
    const float* bo  = (const float*)d_in[11];
    const float* bet = (const float*)d_in[12];
    const float* Wp  = (const float*)d_in[13];
    const float* bp  = (const float*)d_in[14];
    float* out = (float*)d_out;

    const size_t smem = (size_t)(4 * TPB * RS + H + TPB) * sizeof(float);
    cudaFuncSetAttribute(dango_fused_kernel,
                         cudaFuncAttributeMaxDynamicSharedMemorySize, (int)smem);

    dango_fused_kernel<<<GROUPS / GPB, NTHREADS, smem>>>(
        X0, Ws, bs, Wq, bq, Wk, bk, Wv, bv, Wo, bo, bet, Wp, bp, out);
}

// round 2
// speedup vs baseline: 1.1974x; 1.1974x over previous
#include <cuda_runtime.h>

// ---------------------------------------------------------------------------
// GeneInteractionDango fused kernel v2: packed f32x2 FMAs + smem weight staging
//
// One block = 32 groups (96 tokens). 3 state buffers [96][132] in smem plus a
// 64KB packed weight buffer. Each of the 9 GEMMs: stage W once per block
// (k-pair interleaved packing), then a pure-LDS inner loop with fma.rn.f32x2
// (two fp32 MACs per instruction, two k-partial sums per output, reduced at
// the end). Exact fp32 arithmetic throughout.
// ---------------------------------------------------------------------------

#define GROUPS   131072
#define SEQ      3
#define H        128
#define NH       4
#define HD       32
#define NLAYERS  2
#define GPB      32
#define TPB      96
#define RS       132              // row stride (floats): %4==0 for float4, 132%32=4 banks
#define NTHREADS 256
#define KP       64               // number of k-pairs

typedef unsigned long long u64;

__device__ __forceinline__ u64 pack2(float lo, float hi) {
    u64 r;
    asm("mov.b64 %0, {%1, %2};" : "=l"(r) : "f"(lo), "f"(hi));
    return r;
}
__device__ __forceinline__ void unpack2(u64 v, float& lo, float& hi) {
    asm("mov.b64 {%0, %1}, %2;" : "=f"(lo), "=f"(hi) : "l"(v));
}
__device__ __forceinline__ void ffma2(u64& d, u64 a, u64 b) {
    asm("fma.rn.f32x2 %0, %1, %2, %0;" : "+l"(d) : "l"(a), "l"(b));
}

// Stage W[128][128] (row k, col j) into Wb packed: Wb[kp*128+j] = (W[2kp][j], W[2kp+1][j])
__device__ __forceinline__ void stage_weights(const float* __restrict__ Wg,
                                              u64* __restrict__ Wb, int tid)
{
#pragma unroll
    for (int s = 0; s < 4; s++) {
        int slot = tid + s * NTHREADS;       // 0..1023
        int kp = slot >> 4;                  // 0..63
        int jg = slot & 15;                  // 0..15 (8 columns each)
        const float* r0 = Wg + (2 * kp) * H + jg * 8;
        const float* r1 = r0 + H;
        float4 a0 = __ldg((const float4*)r0);
        float4 a1 = __ldg((const float4*)(r0 + 4));
        float4 b0 = __ldg((const float4*)r1);
        float4 b1 = __ldg((const float4*)(r1 + 4));
        u64* dst = Wb + kp * H + jg * 8;
        dst[0] = pack2(a0.x, b0.x); dst[1] = pack2(a0.y, b0.y);
        dst[2] = pack2(a0.z, b0.z); dst[3] = pack2(a0.w, b0.w);
        dst[4] = pack2(a1.x, b1.x); dst[5] = pack2(a1.y, b1.y);
        dst[6] = pack2(a1.z, b1.z); dst[7] = pack2(a1.w, b1.w);
    }
}

// Thread tile: 6 tokens (rows t*16+ty) x 8 outputs (cols tx*8..tx*8+7).
// MODE 0: Y = acc + b ; MODE 1: Y = relu(acc + b) ; MODE 2: Y += beta*(acc + b)
template <int MODE>
__device__ __forceinline__ void gemm_tile(const float* __restrict__ Xin,
                                          const u64* __restrict__ Wb,
                                          const float* __restrict__ gbias,
                                          float* __restrict__ Yout,
                                          int tx, int ty, float betaVal)
{
    u64 acc[6][8];
#pragma unroll
    for (int t = 0; t < 6; t++)
#pragma unroll
        for (int j = 0; j < 8; j++) acc[t][j] = 0ull;

    const u64* wrow = Wb + tx * 8;

#pragma unroll 2
    for (int kp = 0; kp < KP; kp++) {
        ulonglong2 w0 = *(const ulonglong2*)(wrow + kp * H + 0);
        ulonglong2 w1 = *(const ulonglong2*)(wrow + kp * H + 2);
        ulonglong2 w2 = *(const ulonglong2*)(wrow + kp * H + 4);
        ulonglong2 w3 = *(const ulonglong2*)(wrow + kp * H + 6);
#pragma unroll
        for (int t = 0; t < 6; t++) {
            u64 xv = *(const u64*)(Xin + (t * 16 + ty) * RS + 2 * kp);
            ffma2(acc[t][0], xv, w0.x); ffma2(acc[t][1], xv, w0.y);
            ffma2(acc[t][2], xv, w1.x); ffma2(acc[t][3], xv, w1.y);
            ffma2(acc[t][4], xv, w2.x); ffma2(acc[t][5], xv, w2.y);
            ffma2(acc[t][6], xv, w3.x); ffma2(acc[t][7], xv, w3.y);
        }
    }

    float bb[8];
#pragma unroll
    for (int j = 0; j < 8; j++) bb[j] = __ldg(gbias + tx * 8 + j);

#pragma unroll
    for (int t = 0; t < 6; t++) {
        float* yrow = Yout + (t * 16 + ty) * RS + tx * 8;
        float r[8];
#pragma unroll
        for (int j = 0; j < 8; j++) {
            float lo, hi; unpack2(acc[t][j], lo, hi);
            r[j] = lo + hi + bb[j];
        }
        if (MODE == 0) {
            ((float4*)yrow)[0] = make_float4(r[0], r[1], r[2], r[3]);
            ((float4*)yrow)[1] = make_float4(r[4], r[5], r[6], r[7]);
        } else if (MODE == 1) {
            ((float4*)yrow)[0] = make_float4(fmaxf(r[0], 0.f), fmaxf(r[1], 0.f),
                                             fmaxf(r[2], 0.f), fmaxf(r[3], 0.f));
            ((float4*)yrow)[1] = make_float4(fmaxf(r[4], 0.f), fmaxf(r[5], 0.f),
                                             fmaxf(r[6], 0.f), fmaxf(r[7], 0.f));
        } else {
            float4 o0 = ((float4*)yrow)[0];
            float4 o1 = ((float4*)yrow)[1];
            o0.x += betaVal * r[0]; o0.y += betaVal * r[1];
            o0.z += betaVal * r[2]; o0.w += betaVal * r[3];
            o1.x += betaVal * r[4]; o1.y += betaVal * r[5];
            o1.z += betaVal * r[6]; o1.w += betaVal * r[7];
            ((float4*)yrow)[0] = o0;
            ((float4*)yrow)[1] = o1;
        }
    }
}

__global__ __launch_bounds__(NTHREADS, 1)
void dango_fused_v2(const float* __restrict__ X0,
                    const float* __restrict__ Ws, const float* __restrict__ bs,
                    const float* __restrict__ Wq, const float* __restrict__ bq,
                    const float* __restrict__ Wk, const float* __restrict__ bk,
                    const float* __restrict__ Wv, const float* __restrict__ bv,
                    const float* __restrict__ Wo, const float* __restrict__ bo,
                    const float* __restrict__ beta,
                    const float* __restrict__ Wp, const float* __restrict__ bp,
                    float* __restrict__ out)
{
    extern __shared__ float sm[];
    float* Xs  = sm;                         // [96][132] dyn state
    float* Qs  = Xs + TPB * RS;              // [96][132] Q / V / reloaded X0
    float* Ks  = Qs + TPB * RS;              // [96][132] K / attn-out / static
    u64*   Wb  = (u64*)(Ks + TPB * RS);      // [64][128] packed weights (64KB)
    float* sWp = (float*)(Wb + KP * H);      // [128]
    float* sAw = sWp + H;                    // [32*4*3*2] attn probs
    float* sSc = sAw + GPB * NH * SEQ * 2;   // [96]

    const int tid  = threadIdx.x;
    const int warp = tid >> 5;
    const int lane = tid & 31;
    const int tx = (warp & 3) * 4 + (lane & 3);    // 0..15 output tile
    const int ty = (warp >> 2) * 8 + (lane >> 2);  // 0..15 token tile
    const int g0 = blockIdx.x * GPB;
    const size_t base = (size_t)g0 * SEQ * H;

    // ---- load X tile + Wp ----
    for (int idx = tid; idx < TPB * (H / 4); idx += NTHREADS) {
        int row = idx >> 5;
        int c4  = idx & 31;
        float4 v = __ldg((const float4*)(X0 + base + (size_t)row * H + c4 * 4));
        *(float4*)(Xs + row * RS + c4 * 4) = v;
    }
    if (tid < H) sWp[tid] = __ldg(Wp + tid);

    // ---- attention layers ----
    for (int l = 0; l < NLAYERS; l++) {
        const size_t wo_off = (size_t)l * H * H;

        __syncthreads();                       // Wb free, Xs ready
        stage_weights(Wq + wo_off, Wb, tid);
        __syncthreads();
        gemm_tile<0>(Xs, Wb, bq + l * H, Qs, tx, ty, 0.f);

        __syncthreads();
        stage_weights(Wk + wo_off, Wb, tid);
        __syncthreads();
        gemm_tile<0>(Xs, Wb, bk + l * H, Ks, tx, ty, 0.f);

        __syncthreads();
        // stage Wv (indep of Q/K) + compute attention probs in same phase
        stage_weights(Wv + wo_off, Wb, tid);
        if (tid < GPB * NH) {
            const int g = tid >> 2, h = tid & 3;
            const int rb = g * SEQ, ho = h * HD;
            const float inv = 0.17677669529663687f;   // 1/sqrt(32)
#pragma unroll
            for (int qi = 0; qi < SEQ; qi++) {
                const int k0 = (qi == 0) ? 1 : 0;
                const int k1 = (qi == 2) ? 1 : 2;
                const float4* q  = (const float4*)(Qs + (rb + qi) * RS + ho);
                const float4* ka = (const float4*)(Ks + (rb + k0) * RS + ho);
                const float4* kb = (const float4*)(Ks + (rb + k1) * RS + ho);
                float s0 = 0.f, s1 = 0.f;
#pragma unroll
                for (int d = 0; d < 8; d++) {
                    float4 qv = q[d], va = ka[d], vb = kb[d];
                    s0 += qv.x * va.x + qv.y * va.y + qv.z * va.z + qv.w * va.w;
                    s1 += qv.x * vb.x + qv.y * vb.y + qv.z * vb.z + qv.w * vb.w;
                }
                s0 *= inv; s1 *= inv;
                float m  = fmaxf(s0, s1);
                float e0 = expf(s0 - m), e1 = expf(s1 - m);
                float r  = 1.0f / (e0 + e1);
                sAw[(tid * SEQ + qi) * 2 + 0] = e0 * r;
                sAw[(tid * SEQ + qi) * 2 + 1] = e1 * r;
            }
        }
        __syncthreads();
        gemm_tile<0>(Xs, Wb, bv + l * H, Qs, tx, ty, 0.f);   // V into Qs

        __syncthreads();
        // stage Wo + attention combine (V in Qs -> attn out in Ks)
        stage_weights(Wo + wo_off, Wb, tid);
        if (tid < GPB * NH) {
            const int g = tid >> 2, h = tid & 3;
            const int rb = g * SEQ, ho = h * HD;
#pragma unroll
            for (int qi = 0; qi < SEQ; qi++) {
                const int k0 = (qi == 0) ? 1 : 0;
                const int k1 = (qi == 2) ? 1 : 2;
                const float w0 = sAw[(tid * SEQ + qi) * 2 + 0];
                const float w1 = sAw[(tid * SEQ + qi) * 2 + 1];
                const float4* va = (const float4*)(Qs + (rb + k0) * RS + ho);
                const float4* vb = (const float4*)(Qs + (rb + k1) * RS + ho);
                float4* o = (float4*)(Ks + (rb + qi) * RS + ho);
#pragma unroll
                for (int d = 0; d < 8; d++) {
                    float4 a = va[d], b = vb[d];
                    o[d] = make_float4(w0 * a.x + w1 * b.x, w0 * a.y + w1 * b.y,
                                       w0 * a.z + w1 * b.z, w0 * a.w + w1 * b.w);
                }
            }
        }
        __syncthreads();
        gemm_tile<2>(Ks, Wb, bo + l * H, Xs, tx, ty, __ldg(beta + l));  // ReZero residual
    }

    // ---- static path: reload X0 -> Qs, stage Ws, static = relu(...) -> Ks ----
    __syncthreads();
    stage_weights(Ws, Wb, tid);
    for (int idx = tid; idx < TPB * (H / 4); idx += NTHREADS) {
        int row = idx >> 5;
        int c4  = idx & 31;
        float4 v = __ldg((const float4*)(X0 + base + (size_t)row * H + c4 * 4));
        *(float4*)(Qs + row * RS + c4 * 4) = v;
    }
    __syncthreads();
    gemm_tile<1>(Qs, Wb, bs, Ks, tx, ty, 0.f);
    __syncthreads();

    // ---- per-token score ----
    if (tid < TPB) {
        const float4* drow = (const float4*)(Xs + tid * RS);
        const float4* srow = (const float4*)(Ks + tid * RS);
        const float4* wrow = (const float4*)sWp;
        float s = 0.0f;
#pragma unroll
        for (int j = 0; j < 32; j++) {
            float4 d = drow[j], st = srow[j], w = wrow[j];
            float dx = d.x - st.x, dy = d.y - st.y, dz = d.z - st.z, dw = d.w - st.w;
            s += dx * dx * w.x + dy * dy * w.y + dz * dz * w.z + dw * dw * w.w;
        }
        sSc[tid] = s + __ldg(bp);
    }
    __syncthreads();

    if (tid < GPB) {
        float v = (sSc[tid * 3] + sSc[tid * 3 + 1] + sSc[tid * 3 + 2]) * (1.0f / 3.0f);
        out[g0 + tid] = v;
    }
}

extern "C" void kernel_launch(void* const* d_in, const int* in_sizes, int n_in,
                              void* d_out, int out_size)
{
    const float* X0  = (const float*)d_in[0];
    // d_in[1] = batch (int64) — implicit: repeat(arange(G), 3)
    const float* Ws  = (const float*)d_in[2];
    const float* bs  = (const float*)d_in[3];
    const float* Wq  = (const float*)d_in[4];
    const float* bq  = (const float*)d_in[5];
    const float* Wk  = (const float*)d_in[6];
    const float* bk  = (const float*)d_in[7];
    const float* Wv  = (const float*)d_in[8];
    const float* bv  = (const float*)d_in[9];
    const float* Wo  = (const float*)d_in[10];
    const float* bo  = (const float*)d_in[11];
    const float* bet = (const float*)d_in[12];
    const float* Wp  = (const float*)d_in[13];
    const float* bp  = (const float*)d_in[14];
    float* out = (float*)d_out;

    const size_t smem = (size_t)(3 * TPB * RS) * sizeof(float)   // state buffers
                      + (size_t)(KP * H) * sizeof(u64)           // packed weights 64KB
                      + (size_t)(H + GPB * NH * SEQ * 2 + TPB) * sizeof(float);
    cudaFuncSetAttribute(dango_fused_v2,
                         cudaFuncAttributeMaxDynamicSharedMemorySize, (int)smem);

    dango_fused_v2<<<GROUPS / GPB, NTHREADS, smem>>>(
        X0, Ws, bs, Wq, bq, Wk, bk, Wv, bv, Wo, bo, bet, Wp, bp, out);
}

// round 3
// speedup vs baseline: 1.2013x; 1.0032x over previous
#include <cuda_runtime.h>

// ---------------------------------------------------------------------------
// GeneInteractionDango fused kernel v2: packed f32x2 FMAs + smem weight staging
//
// One block = 32 groups (96 tokens). 3 state buffers [96][132] in smem plus a
// 64KB packed weight buffer. Each of the 9 GEMMs: stage W once per block
// (k-pair interleaved packing), then a pure-LDS inner loop with fma.rn.f32x2
// (two fp32 MACs per instruction, two k-partial sums per output, reduced at
// the end). Exact fp32 arithmetic throughout.
// ---------------------------------------------------------------------------

#define GROUPS   131072
#define SEQ      3
#define H        128
#define NH       4
#define HD       32
#define NLAYERS  2
#define GPB      32
#define TPB      96
#define RS       132              // row stride (floats): %4==0 for float4, 132%32=4 banks
#define NTHREADS 256
#define KP       64               // number of k-pairs

typedef unsigned long long u64;

__device__ __forceinline__ u64 pack2(float lo, float hi) {
    u64 r;
    asm("mov.b64 %0, {%1, %2};" : "=l"(r) : "f"(lo), "f"(hi));
    return r;
}
__device__ __forceinline__ void unpack2(u64 v, float& lo, float& hi) {
    asm("mov.b64 {%0, %1}, %2;" : "=f"(lo), "=f"(hi) : "l"(v));
}
__device__ __forceinline__ void ffma2(u64& d, u64 a, u64 b) {
    asm("fma.rn.f32x2 %0, %1, %2, %0;" : "+l"(d) : "l"(a), "l"(b));
}

// Stage W[128][128] (row k, col j) into Wb packed: Wb[kp*128+j] = (W[2kp][j], W[2kp+1][j])
__device__ __forceinline__ void stage_weights(const float* __restrict__ Wg,
                                              u64* __restrict__ Wb, int tid)
{
#pragma unroll
    for (int s = 0; s < 4; s++) {
        int slot = tid + s * NTHREADS;       // 0..1023
        int kp = slot >> 4;                  // 0..63
        int jg = slot & 15;                  // 0..15 (8 columns each)
        const float* r0 = Wg + (2 * kp) * H + jg * 8;
        const float* r1 = r0 + H;
        float4 a0 = __ldg((const float4*)r0);
        float4 a1 = __ldg((const float4*)(r0 + 4));
        float4 b0 = __ldg((const float4*)r1);
        float4 b1 = __ldg((const float4*)(r1 + 4));
        u64* dst = Wb + kp * H + jg * 8;
        dst[0] = pack2(a0.x, b0.x); dst[1] = pack2(a0.y, b0.y);
        dst[2] = pack2(a0.z, b0.z); dst[3] = pack2(a0.w, b0.w);
        dst[4] = pack2(a1.x, b1.x); dst[5] = pack2(a1.y, b1.y);
        dst[6] = pack2(a1.z, b1.z); dst[7] = pack2(a1.w, b1.w);
    }
}

// Thread tile: 6 tokens (rows t*16+ty) x 8 outputs (cols tx*8..tx*8+7).
// MODE 0: Y = acc + b ; MODE 1: Y = relu(acc + b) ; MODE 2: Y += beta*(acc + b)
template <int MODE>
__device__ __forceinline__ void gemm_tile(const float* __restrict__ Xin,
                                          const u64* __restrict__ Wb,
                                          const float* __restrict__ gbias,
                                          float* __restrict__ Yout,
                                          int tx, int ty, float betaVal)
{
    u64 acc[6][8];
#pragma unroll
    for (int t = 0; t < 6; t++)
#pragma unroll
        for (int j = 0; j < 8; j++) acc[t][j] = 0ull;

    const u64* wrow = Wb + tx * 8;

#pragma unroll 2
    for (int kp = 0; kp < KP; kp++) {
        ulonglong2 w0 = *(const ulonglong2*)(wrow + kp * H + 0);
        ulonglong2 w1 = *(const ulonglong2*)(wrow + kp * H + 2);
        ulonglong2 w2 = *(const ulonglong2*)(wrow + kp * H + 4);
        ulonglong2 w3 = *(const ulonglong2*)(wrow + kp * H + 6);
#pragma unroll
        for (int t = 0; t < 6; t++) {
            u64 xv = *(const u64*)(Xin + (t * 16 + ty) * RS + 2 * kp);
            ffma2(acc[t][0], xv, w0.x); ffma2(acc[t][1], xv, w0.y);
            ffma2(acc[t][2], xv, w1.x); ffma2(acc[t][3], xv, w1.y);
            ffma2(acc[t][4], xv, w2.x); ffma2(acc[t][5], xv, w2.y);
            ffma2(acc[t][6], xv, w3.x); ffma2(acc[t][7], xv, w3.y);
        }
    }

    float bb[8];
#pragma unroll
    for (int j = 0; j < 8; j++) bb[j] = __ldg(gbias + tx * 8 + j);

#pragma unroll
    for (int t = 0; t < 6; t++) {
        float* yrow = Yout + (t * 16 + ty) * RS + tx * 8;
        float r[8];
#pragma unroll
        for (int j = 0; j < 8; j++) {
            float lo, hi; unpack2(acc[t][j], lo, hi);
            r[j] = lo + hi + bb[j];
        }
        if (MODE == 0) {
            ((float4*)yrow)[0] = make_float4(r[0], r[1], r[2], r[3]);
            ((float4*)yrow)[1] = make_float4(r[4], r[5], r[6], r[7]);
        } else if (MODE == 1) {
            ((float4*)yrow)[0] = make_float4(fmaxf(r[0], 0.f), fmaxf(r[1], 0.f),
                                             fmaxf(r[2], 0.f), fmaxf(r[3], 0.f));
            ((float4*)yrow)[1] = make_float4(fmaxf(r[4], 0.f), fmaxf(r[5], 0.f),
                                             fmaxf(r[6], 0.f), fmaxf(r[7], 0.f));
        } else {
            float4 o0 = ((float4*)yrow)[0];
            float4 o1 = ((float4*)yrow)[1];
            o0.x += betaVal * r[0]; o0.y += betaVal * r[1];
            o0.z += betaVal * r[2]; o0.w += betaVal * r[3];
            o1.x += betaVal * r[4]; o1.y += betaVal * r[5];
            o1.z += betaVal * r[6]; o1.w += betaVal * r[7];
            ((float4*)yrow)[0] = o0;
            ((float4*)yrow)[1] = o1;
        }
    }
}

__global__ __launch_bounds__(NTHREADS, 1)
void dango_fused_v2(const float* __restrict__ X0,
                    const float* __restrict__ Ws, const float* __restrict__ bs,
                    const float* __restrict__ Wq, const float* __restrict__ bq,
                    const float* __restrict__ Wk, const float* __restrict__ bk,
                    const float* __restrict__ Wv, const float* __restrict__ bv,
                    const float* __restrict__ Wo, const float* __restrict__ bo,
                    const float* __restrict__ beta,
                    const float* __restrict__ Wp, const float* __restrict__ bp,
                    float* __restrict__ out)
{
    extern __shared__ float sm[];
    float* Xs  = sm;                         // [96][132] dyn state
    float* Qs  = Xs + TPB * RS;              // [96][132] Q / V / reloaded X0
    float* Ks  = Qs + TPB * RS;              // [96][132] K / attn-out / static
    u64*   Wb  = (u64*)(Ks + TPB * RS);      // [64][128] packed weights (64KB)
    float* sWp = (float*)(Wb + KP * H);      // [128]
    float* sAw = sWp + H;                    // [32*4*3*2] attn probs
    float* sSc = sAw + GPB * NH * SEQ * 2;   // [96]

    const int tid  = threadIdx.x;
    const int warp = tid >> 5;
    const int lane = tid & 31;
    const int tx = (warp & 3) * 4 + (lane & 3);    // 0..15 output tile
    const int ty = (warp >> 2) * 8 + (lane >> 2);  // 0..15 token tile
    const int g0 = blockIdx.x * GPB;
    const size_t base = (size_t)g0 * SEQ * H;

    // ---- load X tile + Wp ----
    for (int idx = tid; idx < TPB * (H / 4); idx += NTHREADS) {
        int row = idx >> 5;
        int c4  = idx & 31;
        float4 v = __ldg((const float4*)(X0 + base + (size_t)row * H + c4 * 4));
        *(float4*)(Xs + row * RS + c4 * 4) = v;
    }
    if (tid < H) sWp[tid] = __ldg(Wp + tid);

    // ---- attention layers ----
    for (int l = 0; l < NLAYERS; l++) {
        const size_t wo_off = (size_t)l * H * H;

        __syncthreads();                       // Wb free, Xs ready
        stage_weights(Wq + wo_off, Wb, tid);
        __syncthreads();
        gemm_tile<0>(Xs, Wb, bq + l * H, Qs, tx, ty, 0.f);

        __syncthreads();
        stage_weights(Wk + wo_off, Wb, tid);
        __syncthreads();
        gemm_tile<0>(Xs, Wb, bk + l * H, Ks, tx, ty, 0.f);

        __syncthreads();
        // stage Wv (indep of Q/K) + compute attention probs in same phase
        stage_weights(Wv + wo_off, Wb, tid);
        if (tid < GPB * NH) {
            const int g = tid >> 2, h = tid & 3;
            const int rb = g * SEQ, ho = h * HD;
            const float inv = 0.17677669529663687f;   // 1/sqrt(32)
#pragma unroll
            for (int qi = 0; qi < SEQ; qi++) {
                const int k0 = (qi == 0) ? 1 : 0;
                const int k1 = (qi == 2) ? 1 : 2;
                const float4* q  = (const float4*)(Qs + (rb + qi) * RS + ho);
                const float4* ka = (const float4*)(Ks + (rb + k0) * RS + ho);
                const float4* kb = (const float4*)(Ks + (rb + k1) * RS + ho);
                float s0 = 0.f, s1 = 0.f;
#pragma unroll
                for (int d = 0; d < 8; d++) {
                    float4 qv = q[d], va = ka[d], vb = kb[d];
                    s0 += qv.x * va.x + qv.y * va.y + qv.z * va.z + qv.w * va.w;
                    s1 += qv.x * vb.x + qv.y * vb.y + qv.z * vb.z + qv.w * vb.w;
                }
                s0 *= inv; s1 *= inv;
                float m  = fmaxf(s0, s1);
                float e0 = expf(s0 - m), e1 = expf(s1 - m);
                float r  = 1.0f / (e0 + e1);
                sAw[(tid * SEQ + qi) * 2 + 0] = e0 * r;
                sAw[(tid * SEQ + qi) * 2 + 1] = e1 * r;
            }
        }
        __syncthreads();
        gemm_tile<0>(Xs, Wb, bv + l * H, Qs, tx, ty, 0.f);   // V into Qs

        __syncthreads();
        // stage Wo + attention combine (V in Qs -> attn out in Ks)
        stage_weights(Wo + wo_off, Wb, tid);
        if (tid < GPB * NH) {
            const int g = tid >> 2, h = tid & 3;
            const int rb = g * SEQ, ho = h * HD;
#pragma unroll
            for (int qi = 0; qi < SEQ; qi++) {
                const int k0 = (qi == 0) ? 1 : 0;
                const int k1 = (qi == 2) ? 1 : 2;
                const float w0 = sAw[(tid * SEQ + qi) * 2 + 0];
                const float w1 = sAw[(tid * SEQ + qi) * 2 + 1];
                const float4* va = (const float4*)(Qs + (rb + k0) * RS + ho);
                const float4* vb = (const float4*)(Qs + (rb + k1) * RS + ho);
                float4* o = (float4*)(Ks + (rb + qi) * RS + ho);
#pragma unroll
                for (int d = 0; d < 8; d++) {
                    float4 a = va[d], b = vb[d];
                    o[d] = make_float4(w0 * a.x + w1 * b.x, w0 * a.y + w1 * b.y,
                                       w0 * a.z + w1 * b.z, w0 * a.w + w1 * b.w);
                }
            }
        }
        __syncthreads();
        gemm_tile<2>(Ks, Wb, bo + l * H, Xs, tx, ty, __ldg(beta + l));  // ReZero residual
    }

    // ---- static path: reload X0 -> Qs, stage Ws, static = relu(...) -> Ks ----
    __syncthreads();
    stage_weights(Ws, Wb, tid);
    for (int idx = tid; idx < TPB * (H / 4); idx += NTHREADS) {
        int row = idx >> 5;
        int c4  = idx & 31;
        float4 v = __ldg((const float4*)(X0 + base + (size_t)row * H + c4 * 4));
        *(float4*)(Qs + row * RS + c4 * 4) = v;
    }
    __syncthreads();
    gemm_tile<1>(Qs, Wb, bs, Ks, tx, ty, 0.f);
    __syncthreads();

    // ---- per-token score ----
    if (tid < TPB) {
        const float4* drow = (const float4*)(Xs + tid * RS);
        const float4* srow = (const float4*)(Ks + tid * RS);
        const float4* wrow = (const float4*)sWp;
        float s = 0.0f;
#pragma unroll
        for (int j = 0; j < 32; j++) {
            float4 d = drow[j], st = srow[j], w = wrow[j];
            float dx = d.x - st.x, dy = d.y - st.y, dz = d.z - st.z, dw = d.w - st.w;
            s += dx * dx * w.x + dy * dy * w.y + dz * dz * w.z + dw * dw * w.w;
        }
        sSc[tid] = s + __ldg(bp);
    }
    __syncthreads();

    if (tid < GPB) {
        float v = (sSc[tid * 3] + sSc[tid * 3 + 1] + sSc[tid * 3 + 2]) * (1.0f / 3.0f);
        out[g0 + tid] = v;
    }
}

extern "C" void kernel_launch(void* const* d_in, const int* in_sizes, int n_in,
                              void* d_out, int out_size)
{
    const float* X0  = (const float*)d_in[0];
    // d_in[1] = batch (int64) — implicit: repeat(arange(G), 3)
    const float* Ws  = (const float*)d_in[2];
    const float* bs  = (const float*)d_in[3];
    const float* Wq  = (const float*)d_in[4];
    const float* bq  = (const float*)d_in[5];
    const float* Wk  = (const float*)d_in[6];
    const float* bk  = (const float*)d_in[7];
    const float* Wv  = (const float*)d_in[8];
    const float* bv  = (const float*)d_in[9];
    const float* Wo  = (const float*)d_in[10];
    const float* bo  = (const float*)d_in[11];
    const float* bet = (const float*)d_in[12];
    const float* Wp  = (const float*)d_in[13];
    const float* bp  = (const float*)d_in[14];
    float* out = (float*)d_out;

    const size_t smem = (size_t)(3 * TPB * RS) * sizeof(float)   // state buffers
                      + (size_t)(KP * H) * sizeof(u64)           // packed weights 64KB
                      + (size_t)(H + GPB * NH * SEQ * 2 + TPB) * sizeof(float);
    cudaFuncSetAttribute(dango_fused_v2,
                         cudaFuncAttributeMaxDynamicSharedMemorySize, (int)smem);

    dango_fused_v2<<<GROUPS / GPB, NTHREADS, smem>>>(
        X0, Ws, bs, Wq, bq, Wk, bk, Wv, bv, Wo, bo, bet, Wp, bp, out);
}

// round 4
// speedup vs baseline: 1.3808x; 1.1494x over previous
#include <cuda_runtime.h>

// ---------------------------------------------------------------------------
// GeneInteractionDango fused kernel v3: v2 + bank-conflict-free weight layout.
//
// Column mapping per thread: cols {32c + 2tx + e}, c=0..3, e=0..1 — warp lanes
// with adjacent tx read adjacent u64 pairs in Wb → conflict-free LDS.128 with
// 8-way broadcast. Weight staging is coalesced LDG + conflict-free STS.128.
// Everything else (dataflow, f32x2 FMAs, exact fp32) as v2.
// ---------------------------------------------------------------------------

#define GROUPS   131072
#define SEQ      3
#define H        128
#define NH       4
#define HD       32
#define NLAYERS  2
#define GPB      32
#define TPB      96
#define RS       132              // state row stride (floats)
#define NTHREADS 256
#define KP       64               // k-pairs

typedef unsigned long long u64;

__device__ __forceinline__ u64 pack2(float lo, float hi) {
    u64 r;
    asm("mov.b64 %0, {%1, %2};" : "=l"(r) : "f"(lo), "f"(hi));
    return r;
}
__device__ __forceinline__ void unpack2(u64 v, float& lo, float& hi) {
    asm("mov.b64 {%0, %1}, %2;" : "=f"(lo), "=f"(hi) : "l"(v));
}
__device__ __forceinline__ void ffma2(u64& d, u64 a, u64 b) {
    asm("fma.rn.f32x2 %0, %1, %2, %0;" : "+l"(d) : "l"(a), "l"(b));
}

// Stage W[128][128] into Wb[kp*128 + j] = (W[2kp][j], W[2kp+1][j]).
// slot s -> kp = s>>6, j-pair m = s&63 (j = 2m, 2m+1).
// Lanes get consecutive m: coalesced LDG.64, conflict-free STS.128.
__device__ __forceinline__ void stage_weights(const float* __restrict__ Wg,
                                              u64* __restrict__ Wb, int tid)
{
#pragma unroll
    for (int i = 0; i < 16; i++) {
        int s  = tid + i * NTHREADS;     // 0..4095
        int kp = s >> 6;
        int m  = s & 63;
        float2 a = __ldg((const float2*)(Wg + (2 * kp)     * H + 2 * m));
        float2 b = __ldg((const float2*)(Wg + (2 * kp + 1) * H + 2 * m));
        ulonglong2 v;
        v.x = pack2(a.x, b.x);
        v.y = pack2(a.y, b.y);
        *(ulonglong2*)(Wb + kp * H + 2 * m) = v;
    }
}

// Thread tile: 6 tokens (rows t*16+ty) x 8 outputs (cols 32c+2tx+e).
// MODE 0: Y = acc + b ; MODE 1: Y = relu(acc + b) ; MODE 2: Y += beta*(acc + b)
template <int MODE>
__device__ __forceinline__ void gemm_tile(const float* __restrict__ Xin,
                                          const u64* __restrict__ Wb,
                                          const float* __restrict__ gbias,
                                          float* __restrict__ Yout,
                                          int tx, int ty, float betaVal)
{
    u64 acc[6][8];
#pragma unroll
    for (int t = 0; t < 6; t++)
#pragma unroll
        for (int j = 0; j < 8; j++) acc[t][j] = 0ull;

    const u64* wbase = Wb + 2 * tx;

#pragma unroll 2
    for (int kp = 0; kp < KP; kp++) {
        ulonglong2 w0 = *(const ulonglong2*)(wbase + kp * H + 0);
        ulonglong2 w1 = *(const ulonglong2*)(wbase + kp * H + 32);
        ulonglong2 w2 = *(const ulonglong2*)(wbase + kp * H + 64);
        ulonglong2 w3 = *(const ulonglong2*)(wbase + kp * H + 96);
#pragma unroll
        for (int t = 0; t < 6; t++) {
            u64 xv = *(const u64*)(Xin + (t * 16 + ty) * RS + 2 * kp);
            ffma2(acc[t][0], xv, w0.x); ffma2(acc[t][1], xv, w0.y);
            ffma2(acc[t][2], xv, w1.x); ffma2(acc[t][3], xv, w1.y);
            ffma2(acc[t][4], xv, w2.x); ffma2(acc[t][5], xv, w2.y);
            ffma2(acc[t][6], xv, w3.x); ffma2(acc[t][7], xv, w3.y);
        }
    }

    float bb[8];
#pragma unroll
    for (int c = 0; c < 4; c++) {
        bb[2 * c + 0] = __ldg(gbias + 32 * c + 2 * tx + 0);
        bb[2 * c + 1] = __ldg(gbias + 32 * c + 2 * tx + 1);
    }

#pragma unroll
    for (int t = 0; t < 6; t++) {
        float* yrow = Yout + (t * 16 + ty) * RS + 2 * tx;
#pragma unroll
        for (int c = 0; c < 4; c++) {
            float lo0, hi0, lo1, hi1;
            unpack2(acc[t][2 * c + 0], lo0, hi0);
            unpack2(acc[t][2 * c + 1], lo1, hi1);
            float r0 = lo0 + hi0 + bb[2 * c + 0];
            float r1 = lo1 + hi1 + bb[2 * c + 1];
            float2* yp = (float2*)(yrow + 32 * c);
            if (MODE == 0) {
                *yp = make_float2(r0, r1);
            } else if (MODE == 1) {
                *yp = make_float2(fmaxf(r0, 0.f), fmaxf(r1, 0.f));
            } else {
                float2 o = *yp;
                o.x += betaVal * r0;
                o.y += betaVal * r1;
                *yp = o;
            }
        }
    }
}

__global__ __launch_bounds__(NTHREADS, 1)
void dango_fused_v3(const float* __restrict__ X0,
                    const float* __restrict__ Ws, const float* __restrict__ bs,
                    const float* __restrict__ Wq, const float* __restrict__ bq,
                    const float* __restrict__ Wk, const float* __restrict__ bk,
                    const float* __restrict__ Wv, const float* __restrict__ bv,
                    const float* __restrict__ Wo, const float* __restrict__ bo,
                    const float* __restrict__ beta,
                    const float* __restrict__ Wp, const float* __restrict__ bp,
                    float* __restrict__ out)
{
    extern __shared__ float sm[];
    float* Xs  = sm;                         // [96][132] dyn state
    float* Qs  = Xs + TPB * RS;              // [96][132] Q / V / reloaded X0
    float* Ks  = Qs + TPB * RS;              // [96][132] K / attn-out / static
    u64*   Wb  = (u64*)(Ks + TPB * RS);      // [64][128] packed weights (64KB)
    float* sWp = (float*)(Wb + KP * H);      // [128]
    float* sAw = sWp + H;                    // [32*4*3*2] attn probs
    float* sSc = sAw + GPB * NH * SEQ * 2;   // [96]

    const int tid  = threadIdx.x;
    const int warp = tid >> 5;
    const int lane = tid & 31;
    const int tx = (warp & 3) * 4 + (lane & 3);    // 0..15 output tile
    const int ty = (warp >> 2) * 8 + (lane >> 2);  // 0..15 token tile
    const int g0 = blockIdx.x * GPB;
    const size_t base = (size_t)g0 * SEQ * H;

    // ---- load X tile + Wp ----
    for (int idx = tid; idx < TPB * (H / 4); idx += NTHREADS) {
        int row = idx >> 5;
        int c4  = idx & 31;
        float4 v = __ldg((const float4*)(X0 + base + (size_t)row * H + c4 * 4));
        *(float4*)(Xs + row * RS + c4 * 4) = v;
    }
    if (tid < H) sWp[tid] = __ldg(Wp + tid);

    // ---- attention layers ----
    for (int l = 0; l < NLAYERS; l++) {
        const size_t wo_off = (size_t)l * H * H;

        __syncthreads();                       // Wb free, Xs ready
        stage_weights(Wq + wo_off, Wb, tid);
        __syncthreads();
        gemm_tile<0>(Xs, Wb, bq + l * H, Qs, tx, ty, 0.f);

        __syncthreads();
        stage_weights(Wk + wo_off, Wb, tid);
        __syncthreads();
        gemm_tile<0>(Xs, Wb, bk + l * H, Ks, tx, ty, 0.f);

        __syncthreads();
        // stage Wv + compute attention probs in same phase
        stage_weights(Wv + wo_off, Wb, tid);
        if (tid < GPB * NH) {
            const int g = tid >> 2, h = tid & 3;
            const int rb = g * SEQ, ho = h * HD;
            const float inv = 0.17677669529663687f;   // 1/sqrt(32)
#pragma unroll
            for (int qi = 0; qi < SEQ; qi++) {
                const int k0 = (qi == 0) ? 1 : 0;
                const int k1 = (qi == 2) ? 1 : 2;
                const float4* q  = (const float4*)(Qs + (rb + qi) * RS + ho);
                const float4* ka = (const float4*)(Ks + (rb + k0) * RS + ho);
                const float4* kb = (const float4*)(Ks + (rb + k1) * RS + ho);
                float s0 = 0.f, s1 = 0.f;
#pragma unroll
                for (int d = 0; d < 8; d++) {
                    float4 qv = q[d], va = ka[d], vb = kb[d];
                    s0 += qv.x * va.x + qv.y * va.y + qv.z * va.z + qv.w * va.w;
                    s1 += qv.x * vb.x + qv.y * vb.y + qv.z * vb.z + qv.w * vb.w;
                }
                s0 *= inv; s1 *= inv;
                float m  = fmaxf(s0, s1);
                float e0 = expf(s0 - m), e1 = expf(s1 - m);
                float r  = 1.0f / (e0 + e1);
                sAw[(tid * SEQ + qi) * 2 + 0] = e0 * r;
                sAw[(tid * SEQ + qi) * 2 + 1] = e1 * r;
            }
        }
        __syncthreads();
        gemm_tile<0>(Xs, Wb, bv + l * H, Qs, tx, ty, 0.f);   // V into Qs

        __syncthreads();
        // stage Wo + attention combine (V in Qs -> attn out in Ks)
        stage_weights(Wo + wo_off, Wb, tid);
        if (tid < GPB * NH) {
            const int g = tid >> 2, h = tid & 3;
            const int rb = g * SEQ, ho = h * HD;
#pragma unroll
            for (int qi = 0; qi < SEQ; qi++) {
                const int k0 = (qi == 0) ? 1 : 0;
                const int k1 = (qi == 2) ? 1 : 2;
                const float w0 = sAw[(tid * SEQ + qi) * 2 + 0];
                const float w1 = sAw[(tid * SEQ + qi) * 2 + 1];
                const float4* va = (const float4*)(Qs + (rb + k0) * RS + ho);
                const float4* vb = (const float4*)(Qs + (rb + k1) * RS + ho);
                float4* o = (float4*)(Ks + (rb + qi) * RS + ho);
#pragma unroll
                for (int d = 0; d < 8; d++) {
                    float4 a = va[d], b = vb[d];
                    o[d] = make_float4(w0 * a.x + w1 * b.x, w0 * a.y + w1 * b.y,
                                       w0 * a.z + w1 * b.z, w0 * a.w + w1 * b.w);
                }
            }
        }
        __syncthreads();
        gemm_tile<2>(Ks, Wb, bo + l * H, Xs, tx, ty, __ldg(beta + l));  // ReZero
    }

    // ---- static path: reload X0 -> Qs, stage Ws, static = relu(...) -> Ks ----
    __syncthreads();
    stage_weights(Ws, Wb, tid);
    for (int idx = tid; idx < TPB * (H / 4); idx += NTHREADS) {
        int row = idx >> 5;
        int c4  = idx & 31;
        float4 v = __ldg((const float4*)(X0 + base + (size_t)row * H + c4 * 4));
        *(float4*)(Qs + row * RS + c4 * 4) = v;
    }
    __syncthreads();
    gemm_tile<1>(Qs, Wb, bs, Ks, tx, ty, 0.f);
    __syncthreads();

    // ---- per-token score ----
    if (tid < TPB) {
        const float4* drow = (const float4*)(Xs + tid * RS);
        const float4* srow = (const float4*)(Ks + tid * RS);
        const float4* wrow = (const float4*)sWp;
        float s = 0.0f;
#pragma unroll
        for (int j = 0; j < 32; j++) {
            float4 d = drow[j], st = srow[j], w = wrow[j];
            float dx = d.x - st.x, dy = d.y - st.y, dz = d.z - st.z, dw = d.w - st.w;
            s += dx * dx * w.x + dy * dy * w.y + dz * dz * w.z + dw * dw * w.w;
        }
        sSc[tid] = s + __ldg(bp);
    }
    __syncthreads();

    if (tid < GPB) {
        float v = (sSc[tid * 3] + sSc[tid * 3 + 1] + sSc[tid * 3 + 2]) * (1.0f / 3.0f);
        out[g0 + tid] = v;
    }
}

extern "C" void kernel_launch(void* const* d_in, const int* in_sizes, int n_in,
                              void* d_out, int out_size)
{
    const float* X0  = (const float*)d_in[0];
    // d_in[1] = batch (int64) — implicit: repeat(arange(G), 3)
    const float* Ws  = (const float*)d_in[2];
    const float* bs  = (const float*)d_in[3];
    const float* Wq  = (const float*)d_in[4];
    const float* bq  = (const float*)d_in[5];
    const float* Wk  = (const float*)d_in[6];
    const float* bk  = (const float*)d_in[7];
    const float* Wv  = (const float*)d_in[8];
    const float* bv  = (const float*)d_in[9];
    const float* Wo  = (const float*)d_in[10];
    const float* bo  = (const float*)d_in[11];
    const float* bet = (const float*)d_in[12];
    const float* Wp  = (const float*)d_in[13];
    const float* bp  = (const float*)d_in[14];
    float* out = (float*)d_out;

    const size_t smem = (size_t)(3 * TPB * RS) * sizeof(float)
                      + (size_t)(KP * H) * sizeof(u64)
                      + (size_t)(H + GPB * NH * SEQ * 2 + TPB) * sizeof(float);
    cudaFuncSetAttribute(dango_fused_v3,
                         cudaFuncAttributeMaxDynamicSharedMemorySize, (int)smem);

    dango_fused_v3<<<GROUPS / GPB, NTHREADS, smem>>>(
        X0, Ws, bs, Wq, bq, Wk, bk, Wv, bv, Wo, bo, bet, Wp, bp, out);
}

// round 6
// speedup vs baseline: 5.1559x; 3.7340x over previous
#include <cuda_runtime.h>
#include <cuda_bf16.h>
#include <cstdint>

// ---------------------------------------------------------------------------
// GeneInteractionDango v5: warp-level HMMA (mma.sync m16n8k16 bf16) GEMMs.
// tcgen05 is unusable (harness PTX target is compute_103, no 'a' features);
// mma.sync is baseline PTX and runs on the tensor pipe.
//
// One block = 32 groups (96 tokens = 6 m16 stripes). 8 warps, each owns
// 3 (m16 x n32) tiles sharing one n-quarter (B frags reused across tiles).
// B images [n][k] bf16 prepped in global scratch; double-buffered in smem.
// Static GEMM: 3 accumulated hi/lo bf16 passes for fp32-like precision.
// ---------------------------------------------------------------------------

#define GROUPS   131072
#define SEQ      3
#define H        128
#define GPB      32
#define TPB      96
#define NTHREADS 256

#define XSTR     132      // Xs f32 row stride (floats)
#define BSTR     136      // bf16 row stride (elements); 272B = 4 banks mod 32

// smem byte offsets
#define XS_OFF   0                     // f32 [96][132]  = 50688
#define AB_OFF   50688                 // bf16 [96][136] = 26112
#define BB0_OFF  76800                 // bf16 [128][136] = 34816
#define BB1_OFF  111616                // bf16 [128][136] = 34816
#define QB_OFF   146432                // bf16 [96][136]  (alias: Alo in static)
#define KB_OFF   172544                // bf16 [96][136]
#define VB_OFF   198656                // bf16 [96][136]
#define WP_OFF   224768                // f32[128]
#define BS_OFF   225280                // f32[128]
#define B_OFF    225792                // f32[1024]  (l*512 + {q,k,v,o}*128)
#define SC_OFF   229888                // f32[96]
#define SMEM_SZ  230400

// weight images: 0-7 = {Wq,Wk,Wv,Wo} x layer0, layer1 ; 8 = Ws hi ; 9 = Ws lo
__device__ __align__(16) __nv_bfloat16 g_wt[10][H * H];   // [n][k] = W[k][n]

__device__ __forceinline__ void mma_bf16(float* c,
                                         uint32_t a0, uint32_t a1, uint32_t a2, uint32_t a3,
                                         uint32_t b0, uint32_t b1)
{
    asm volatile(
        "mma.sync.aligned.m16n8k16.row.col.f32.bf16.bf16.f32 "
        "{%0,%1,%2,%3}, {%4,%5,%6,%7}, {%8,%9}, {%0,%1,%2,%3};"
        : "+f"(c[0]), "+f"(c[1]), "+f"(c[2]), "+f"(c[3])
        : "r"(a0), "r"(a1), "r"(a2), "r"(a3), "r"(b0), "r"(b1));
}

__device__ __forceinline__ uint32_t bf16x2(float a, float b) {
    __nv_bfloat162 v = __floats2bfloat162_rn(a, b);
    return *(uint32_t*)&v;
}

// One GEMM pass over this warp's 3 tiles, accumulating into acc[3][4][4].
// A: bf16 [96][BSTR] row-major; B: bf16 [128][BSTR] as [n][k] (col-major B).
__device__ __forceinline__ void gemm3(const unsigned char* __restrict__ smA,
                                      const unsigned char* __restrict__ smB,
                                      int n0, int mb, int g, int tg,
                                      float acc[3][4][4])
{
#pragma unroll
    for (int ks = 0; ks < 8; ks++) {
        const int kb = ks * 32 + tg * 4;     // byte offset within row: 2*(16ks+2tg)
        uint32_t b0[4], b1[4];
#pragma unroll
        for (int j = 0; j < 4; j++) {
            const unsigned char* bp = smB + (uint32_t)(n0 + 8 * j + g) * 272u + kb;
            b0[j] = *(const uint32_t*)bp;
            b1[j] = *(const uint32_t*)(bp + 16);
        }
#pragma unroll
        for (int i = 0; i < 3; i++) {
            const unsigned char* ap = smA + (uint32_t)(mb + 32 * i + g) * 272u + kb;
            uint32_t a0 = *(const uint32_t*)ap;
            uint32_t a1 = *(const uint32_t*)(ap + 8 * 272);
            uint32_t a2 = *(const uint32_t*)(ap + 16);
            uint32_t a3 = *(const uint32_t*)(ap + 8 * 272 + 16);
#pragma unroll
            for (int j = 0; j < 4; j++)
                mma_bf16(acc[i][j], a0, a1, a2, a3, b0[j], b1[j]);
        }
    }
}

__device__ __forceinline__ void zero_acc(float acc[3][4][4]) {
#pragma unroll
    for (int i = 0; i < 3; i++)
#pragma unroll
        for (int j = 0; j < 4; j++)
#pragma unroll
            for (int e = 0; e < 4; e++) acc[i][j][e] = 0.f;
}

// copy one 128x128 bf16 weight image into smem [128][BSTR]
__device__ __forceinline__ void cp_img(unsigned char* __restrict__ dst,
                                       const __nv_bfloat16* __restrict__ src, int tid)
{
#pragma unroll
    for (int i = 0; i < 8; i++) {
        int q = tid + i * NTHREADS;          // 2048 uint4 (16B = 8 bf16)
        int row = q >> 4, c = q & 15;
        uint4 v = __ldg(((const uint4*)src) + q);
        *(uint4*)(dst + (uint32_t)row * 272u + (uint32_t)c * 16u) = v;
    }
}

// build bf16 A image [96][BSTR] from f32 Xs [96][XSTR]
__device__ __forceinline__ void build_A(const float* __restrict__ Xs,
                                        unsigned char* __restrict__ smA, int tid)
{
#pragma unroll
    for (int i = 0; i < 24; i++) {
        int p = tid + i * NTHREADS;          // 6144 pairs
        int row = p >> 6, cp = p & 63;
        float2 v = *(const float2*)(Xs + row * XSTR + 2 * cp);
        *(uint32_t*)(smA + (uint32_t)row * 272u + (uint32_t)cp * 4u) = bf16x2(v.x, v.y);
    }
}

// epilogue: acc + bias -> bf16 buffer
__device__ __forceinline__ void epi_qkv(const float acc[3][4][4], const float* __restrict__ bias,
                                        unsigned char* __restrict__ dst,
                                        int n0, int mb, int g, int tg)
{
#pragma unroll
    for (int i = 0; i < 3; i++) {
        int r0 = mb + 32 * i + g;
#pragma unroll
        for (int j = 0; j < 4; j++) {
            int c = n0 + 8 * j + 2 * tg;
            float bv0 = bias[c], bv1 = bias[c + 1];
            *(uint32_t*)(dst + (uint32_t)r0 * 272u + 2u * c) =
                bf16x2(acc[i][j][0] + bv0, acc[i][j][1] + bv1);
            *(uint32_t*)(dst + (uint32_t)(r0 + 8) * 272u + 2u * c) =
                bf16x2(acc[i][j][2] + bv0, acc[i][j][3] + bv1);
        }
    }
}

__global__ void dango_prep(const float* __restrict__ Ws,
                           const float* __restrict__ Wq, const float* __restrict__ Wk,
                           const float* __restrict__ Wv, const float* __restrict__ Wo)
{
    int img  = blockIdx.x >> 4;
    int part = blockIdx.x & 15;
    const float* src;
    int lo = 0;
    if (img < 8) {
        int l = img >> 2, m = img & 3;
        src = (m == 0 ? Wq : m == 1 ? Wk : m == 2 ? Wv : Wo) + (size_t)l * H * H;
    } else {
        src = Ws;
        lo = (img == 9);
    }
    __nv_bfloat16* dst = g_wt[img];
#pragma unroll
    for (int i = 0; i < 4; i++) {
        int e = part * 1024 + i * 256 + threadIdx.x;
        int n = e >> 7, k = e & 127;
        float w = __ldg(src + k * H + n);
        __nv_bfloat16 v;
        if (!lo) v = __float2bfloat16(w);
        else {
            __nv_bfloat16 h = __float2bfloat16(w);
            v = __float2bfloat16(w - __bfloat162float(h));
        }
        dst[n * H + k] = v;    // [n][k] = W[k][n]
    }
}

__global__ __launch_bounds__(NTHREADS, 1)
void dango_mma(const float* __restrict__ X0,
               const float* __restrict__ bs_, const float* __restrict__ bq_,
               const float* __restrict__ bk_, const float* __restrict__ bv_,
               const float* __restrict__ bo_, const float* __restrict__ beta,
               const float* __restrict__ Wp, const float* __restrict__ bp,
               float* __restrict__ out)
{
    extern __shared__ unsigned char sm[];
    float*         Xs  = (float*)(sm + XS_OFF);
    unsigned char* Ab  = sm + AB_OFF;
    unsigned char* BB0 = sm + BB0_OFF;
    unsigned char* BB1 = sm + BB1_OFF;
    unsigned char* Qb  = sm + QB_OFF;
    unsigned char* Kb  = sm + KB_OFF;
    unsigned char* Vb  = sm + VB_OFF;
    float* sWp = (float*)(sm + WP_OFF);
    float* sBs = (float*)(sm + BS_OFF);
    float* sB  = (float*)(sm + B_OFF);
    float* sSc = (float*)(sm + SC_OFF);

    const int tid  = threadIdx.x;
    const int wid  = tid >> 5;
    const int lane = tid & 31;
    const int g    = lane >> 2;      // mma row group
    const int tg   = lane & 3;       // mma thread-in-group
    const int n0   = (wid & 3) * 32; // n-quarter
    const int mb   = (wid >> 2) * 16;// m base (stripes mb, mb+32, mb+64)
    const int g0   = blockIdx.x * GPB;
    const size_t base = (size_t)g0 * SEQ * H;

    // ---- init phase: Xs, consts, A image, first B image ----
    for (int idx = tid; idx < TPB * (H / 4); idx += NTHREADS) {
        int row = idx >> 5, c4 = idx & 31;
        float4 v = __ldg((const float4*)(X0 + base + (size_t)row * H + c4 * 4));
        *(float4*)(Xs + row * XSTR + c4 * 4) = v;
    }
    if (tid < H) { sWp[tid] = __ldg(Wp + tid); sBs[tid] = __ldg(bs_ + tid); }
    for (int j = tid; j < 1024; j += NTHREADS) {
        int l = j >> 9, t = (j >> 7) & 3, c = j & 127;
        const float* p = (t == 0) ? bq_ : (t == 1) ? bk_ : (t == 2) ? bv_ : bo_;
        sB[j] = __ldg(p + l * H + c);
    }
    if (tid < TPB) sSc[tid] = __ldg(bp);
    __syncthreads();
    build_A(Xs, Ab, tid);
    cp_img(BB0, g_wt[0], tid);
    __syncthreads();

    float acc[3][4][4];

    // ---- attention layers ----
    for (int l = 0; l < 2; l++) {
        const float* bias = sB + l * 512;

        // Q (BB0); prefetch Bk -> BB1
        cp_img(BB1, g_wt[l * 4 + 1], tid);
        zero_acc(acc);
        gemm3(Ab, BB0, n0, mb, g, tg, acc);
        epi_qkv(acc, bias + 0, Qb, n0, mb, g, tg);
        __syncthreads();

        // K (BB1); prefetch Bv -> BB0
        cp_img(BB0, g_wt[l * 4 + 2], tid);
        zero_acc(acc);
        gemm3(Ab, BB1, n0, mb, g, tg, acc);
        epi_qkv(acc, bias + 128, Kb, n0, mb, g, tg);
        __syncthreads();

        // V (BB0); prefetch Bo -> BB1
        cp_img(BB1, g_wt[l * 4 + 3], tid);
        zero_acc(acc);
        gemm3(Ab, BB0, n0, mb, g, tg, acc);
        epi_qkv(acc, bias + 256, Vb, n0, mb, g, tg);
        __syncthreads();

        // attention: exclude-self softmax per (group, head) -> Ab (A for O gemm)
        if (tid < GPB * 4) {
            const int grp = tid >> 2, h = tid & 3;
            const int rb = grp * SEQ, ho = h * 32;
            const float inv = 0.17677669529663687f;   // 1/sqrt(32)
#pragma unroll
            for (int qi = 0; qi < SEQ; qi++) {
                const int k0 = (qi == 0) ? 1 : 0;
                const int k1 = (qi == 2) ? 1 : 2;
                const __nv_bfloat162* q  = (const __nv_bfloat162*)(Qb + (uint32_t)(rb + qi) * 272u + 2u * ho);
                const __nv_bfloat162* ka = (const __nv_bfloat162*)(Kb + (uint32_t)(rb + k0) * 272u + 2u * ho);
                const __nv_bfloat162* kb = (const __nv_bfloat162*)(Kb + (uint32_t)(rb + k1) * 272u + 2u * ho);
                float s0 = 0.f, s1 = 0.f;
#pragma unroll
                for (int d = 0; d < 16; d++) {
                    float2 qv = __bfloat1622float2(q[d]);
                    float2 va = __bfloat1622float2(ka[d]);
                    float2 vb = __bfloat1622float2(kb[d]);
                    s0 += qv.x * va.x + qv.y * va.y;
                    s1 += qv.x * vb.x + qv.y * vb.y;
                }
                s0 *= inv; s1 *= inv;
                float mx = fmaxf(s0, s1);
                float e0 = expf(s0 - mx), e1 = expf(s1 - mx);
                float rr = 1.0f / (e0 + e1);
                float w0 = e0 * rr, w1 = e1 * rr;
                const __nv_bfloat162* v0 = (const __nv_bfloat162*)(Vb + (uint32_t)(rb + k0) * 272u + 2u * ho);
                const __nv_bfloat162* v1 = (const __nv_bfloat162*)(Vb + (uint32_t)(rb + k1) * 272u + 2u * ho);
#pragma unroll
                for (int d = 0; d < 16; d++) {
                    float2 a = __bfloat1622float2(v0[d]);
                    float2 b = __bfloat1622float2(v1[d]);
                    *(uint32_t*)(Ab + (uint32_t)(rb + qi) * 272u + 2u * (ho + 2 * d)) =
                        bf16x2(w0 * a.x + w1 * b.x, w0 * a.y + w1 * b.y);
                }
            }
        }
        __syncthreads();

        // O (BB1); prefetch next (layer-1 Bq, or static Ws_hi) -> BB0
        cp_img(BB0, g_wt[l == 0 ? 4 : 8], tid);
        zero_acc(acc);
        gemm3(Ab, BB1, n0, mb, g, tg, acc);
        {
            const float betaL = __ldg(beta + l);
            const float* bo = bias + 384;
#pragma unroll
            for (int i = 0; i < 3; i++) {
                int r0 = mb + 32 * i + g;
#pragma unroll
                for (int j = 0; j < 4; j++) {
                    int c = n0 + 8 * j + 2 * tg;
                    float bv0 = bo[c], bv1 = bo[c + 1];
                    float2* p0 = (float2*)(Xs + r0 * XSTR + c);
                    float2* p1 = (float2*)(Xs + (r0 + 8) * XSTR + c);
                    float2 x0 = *p0, x1 = *p1;
                    x0.x += betaL * (acc[i][j][0] + bv0);
                    x0.y += betaL * (acc[i][j][1] + bv1);
                    x1.x += betaL * (acc[i][j][2] + bv0);
                    x1.y += betaL * (acc[i][j][3] + bv1);
                    *p0 = x0; *p1 = x1;
                }
            }
        }
        __syncthreads();

        if (l == 0) {                 // rebuild A from updated state
            build_A(Xs, Ab, tid);
            __syncthreads();
        }
    }

    // ---- static path: relu(X0 @ Ws + bs) via hi/lo split (3 passes) ----
    // Ahi -> Ab, Alo -> Qb region; Bhi already in BB0; copy Blo -> BB1
    cp_img(BB1, g_wt[9], tid);
#pragma unroll
    for (int i = 0; i < 24; i++) {
        int p = tid + i * NTHREADS;
        int row = p >> 6, cp = p & 63;
        float2 v = __ldg((const float2*)(X0 + base + (size_t)row * H + 2 * cp));
        __nv_bfloat16 h0 = __float2bfloat16(v.x), h1 = __float2bfloat16(v.y);
        float r0 = v.x - __bfloat162float(h0), r1 = v.y - __bfloat162float(h1);
        uint32_t off = (uint32_t)row * 272u + (uint32_t)cp * 4u;
        __nv_bfloat162 hv = __halves2bfloat162(h0, h1);
        *(uint32_t*)(Ab + off) = *(uint32_t*)&hv;
        *(uint32_t*)(Qb + off) = bf16x2(r0, r1);
    }
    __syncthreads();

    zero_acc(acc);
    gemm3(Ab, BB0, n0, mb, g, tg, acc);   // hi*hi
    gemm3(Ab, BB1, n0, mb, g, tg, acc);   // hi*lo
    gemm3(Qb, BB0, n0, mb, g, tg, acc);   // lo*hi

    // score epilogue: sSc[r] += sum_c (dyn - relu(static))^2 * wp[c]
#pragma unroll
    for (int i = 0; i < 3; i++) {
        int r0 = mb + 32 * i + g;
        float sa = 0.f, sb2 = 0.f;
#pragma unroll
        for (int j = 0; j < 4; j++) {
            int c = n0 + 8 * j + 2 * tg;
            float st, d;
            st = fmaxf(acc[i][j][0] + sBs[c], 0.f);     d = Xs[r0 * XSTR + c] - st;       sa  += d * d * sWp[c];
            st = fmaxf(acc[i][j][1] + sBs[c + 1], 0.f); d = Xs[r0 * XSTR + c + 1] - st;   sa  += d * d * sWp[c + 1];
            st = fmaxf(acc[i][j][2] + sBs[c], 0.f);     d = Xs[(r0 + 8) * XSTR + c] - st; sb2 += d * d * sWp[c];
            st = fmaxf(acc[i][j][3] + sBs[c + 1], 0.f); d = Xs[(r0 + 8) * XSTR + c + 1] - st; sb2 += d * d * sWp[c + 1];
        }
        sa  += __shfl_xor_sync(0xffffffffu, sa, 1);
        sa  += __shfl_xor_sync(0xffffffffu, sa, 2);
        sb2 += __shfl_xor_sync(0xffffffffu, sb2, 1);
        sb2 += __shfl_xor_sync(0xffffffffu, sb2, 2);
        if (tg == 0) {
            atomicAdd(&sSc[r0], sa);
            atomicAdd(&sSc[r0 + 8], sb2);
        }
    }
    __syncthreads();

    if (tid < GPB)
        out[g0 + tid] = (sSc[tid * 3] + sSc[tid * 3 + 1] + sSc[tid * 3 + 2]) * (1.0f / 3.0f);
}

extern "C" void kernel_launch(void* const* d_in, const int* in_sizes, int n_in,
                              void* d_out, int out_size)
{
    const float* X0  = (const float*)d_in[0];
    // d_in[1] = batch (int64) — implicit: repeat(arange(G), 3)
    const float* Ws  = (const float*)d_in[2];
    const float* bs  = (const float*)d_in[3];
    const float* Wq  = (const float*)d_in[4];
    const float* bq  = (const float*)d_in[5];
    const float* Wk  = (const float*)d_in[6];
    const float* bk  = (const float*)d_in[7];
    const float* Wv  = (const float*)d_in[8];
    const float* bv  = (const float*)d_in[9];
    const float* Wo  = (const float*)d_in[10];
    const float* bo  = (const float*)d_in[11];
    const float* bet = (const float*)d_in[12];
    const float* Wp  = (const float*)d_in[13];
    const float* bp  = (const float*)d_in[14];
    float* out = (float*)d_out;

    dango_prep<<<160, NTHREADS>>>(Ws, Wq, Wk, Wv, Wo);

    cudaFuncSetAttribute(dango_mma, cudaFuncAttributeMaxDynamicSharedMemorySize, SMEM_SZ);
    dango_mma<<<GROUPS / GPB, NTHREADS, SMEM_SZ>>>(
        X0, bs, bq, bk, bv, bo, bet, Wp, bp, out);
}

// round 8
// speedup vs baseline: 6.2707x; 1.2162x over previous
#include <cuda_runtime.h>
#include <cuda_bf16.h>
#include <cstdint>

// ---------------------------------------------------------------------------
// GeneInteractionDango v7: v6 with cp_img overflow fixed (16 iters, not 17).
// HMMA + ldmatrix + 2 blocks/SM. GPB=16 groups (48 tokens), 128 threads,
// warp = n32 quarter x 3 m16 stripes. Single smem B buffer; weights prepped
// [n][k] bf16 in global scratch. Static GEMM = 3 accumulated hi/lo passes.
// ---------------------------------------------------------------------------

#define GROUPS   131072
#define SEQ      3
#define H        128
#define GPB      16
#define TPB      48
#define NTHREADS 128

#define XSTR     132      // f32 row stride (words); 132 % 32 = 4 banks
#define RB       272u     // bf16 row stride bytes; 68 words % 32 = 4 banks

// smem byte offsets
#define XS_OFF   0        // f32 [48][132] = 25344
#define AB_OFF   25344    // bf16 [48][136] = 13056
#define QB_OFF   38400
#define KB_OFF   51456
#define VB_OFF   64512
#define BB_OFF   77568    // bf16 [128][136] = 34816
#define WP_OFF   112384   // f32[128]
#define BS_OFF   112896   // f32[128]
#define B_OFF    113408   // f32[512] current-layer biases {q,k,v,o}
#define SC_OFF   115456   // f32[48]
#define SMEM_SZ  115648

// weight images: 0-7 = {Wq,Wk,Wv,Wo} x layer ; 8 = Ws hi ; 9 = Ws lo
__device__ __align__(16) __nv_bfloat16 g_wt[10][H * H];   // [n][k] = W[k][n]

__device__ __forceinline__ void mma_bf16(float* c,
                                         uint32_t a0, uint32_t a1, uint32_t a2, uint32_t a3,
                                         uint32_t b0, uint32_t b1)
{
    asm volatile(
        "mma.sync.aligned.m16n8k16.row.col.f32.bf16.bf16.f32 "
        "{%0,%1,%2,%3}, {%4,%5,%6,%7}, {%8,%9}, {%0,%1,%2,%3};"
        : "+f"(c[0]), "+f"(c[1]), "+f"(c[2]), "+f"(c[3])
        : "r"(a0), "r"(a1), "r"(a2), "r"(a3), "r"(b0), "r"(b1));
}

__device__ __forceinline__ void ldsm_x4(uint32_t& r0, uint32_t& r1, uint32_t& r2, uint32_t& r3,
                                        uint32_t addr)
{
    asm volatile("ldmatrix.sync.aligned.m8n8.x4.shared.b16 {%0,%1,%2,%3}, [%4];"
                 : "=r"(r0), "=r"(r1), "=r"(r2), "=r"(r3) : "r"(addr));
}

__device__ __forceinline__ uint32_t smem_u32(const void* p) {
    uint32_t a;
    asm("{ .reg .u64 t; cvta.to.shared.u64 t, %1; cvt.u32.u64 %0, t; }" : "=r"(a) : "l"(p));
    return a;
}

__device__ __forceinline__ uint32_t bf16x2(float a, float b) {
    __nv_bfloat162 v = __floats2bfloat162_rn(a, b);
    return *(uint32_t*)&v;
}

// one [48x128] @ [128x128] pass, warp = 3 m16 stripes x n32, acc += A*B
__device__ __forceinline__ void gemm3(uint32_t aBase, uint32_t bBase,
                                      uint32_t aoff, uint32_t boff0, uint32_t boff1,
                                      float acc[3][4][4])
{
#pragma unroll
    for (int ks = 0; ks < 8; ks++) {
        uint32_t a[3][4];
#pragma unroll
        for (int s = 0; s < 3; s++)
            ldsm_x4(a[s][0], a[s][1], a[s][2], a[s][3],
                    aBase + (uint32_t)s * (16u * RB) + aoff + (uint32_t)ks * 32u);
        uint32_t b0[4], b1[4];
        ldsm_x4(b0[0], b1[0], b0[1], b1[1], bBase + boff0 + (uint32_t)ks * 32u);
        ldsm_x4(b0[2], b1[2], b0[3], b1[3], bBase + boff1 + (uint32_t)ks * 32u);
#pragma unroll
        for (int s = 0; s < 3; s++)
#pragma unroll
            for (int j = 0; j < 4; j++)
                mma_bf16(acc[s][j], a[s][0], a[s][1], a[s][2], a[s][3], b0[j], b1[j]);
    }
}

__device__ __forceinline__ void zero_acc(float acc[3][4][4]) {
#pragma unroll
    for (int s = 0; s < 3; s++)
#pragma unroll
        for (int j = 0; j < 4; j++)
#pragma unroll
            for (int e = 0; e < 4; e++) acc[s][j][e] = 0.f;
}

// copy one 128x128 bf16 weight image into smem [128][RB]
// 2048 uint4 = 128 rows x 16 uint4 (256B data per 272B row)
__device__ __forceinline__ void cp_img(unsigned char* __restrict__ dst,
                                       const __nv_bfloat16* __restrict__ src, int tid)
{
#pragma unroll
    for (int i = 0; i < 16; i++) {
        int q = tid + i * NTHREADS;          // 0..2047
        int row = q >> 4, c = q & 15;
        uint4 v = __ldg(((const uint4*)src) + q);
        *(uint4*)(dst + (uint32_t)row * RB + (uint32_t)c * 16u) = v;
    }
}

// bf16 A image [48][RB] from f32 Xs
__device__ __forceinline__ void build_A(const float* __restrict__ Xs,
                                        unsigned char* __restrict__ smA, int tid)
{
#pragma unroll
    for (int i = 0; i < 24; i++) {
        int p = tid + i * NTHREADS;          // 3072 pairs
        int row = p >> 6, cp = p & 63;
        float2 v = *(const float2*)(Xs + row * XSTR + 2 * cp);
        *(uint32_t*)(smA + (uint32_t)row * RB + (uint32_t)cp * 4u) = bf16x2(v.x, v.y);
    }
}

__device__ __forceinline__ void epi_qkv(const float acc[3][4][4], const float* __restrict__ bias,
                                        unsigned char* __restrict__ dst, int n0, int g, int tg)
{
#pragma unroll
    for (int s = 0; s < 3; s++) {
        int r0 = 16 * s + g;
#pragma unroll
        for (int j = 0; j < 4; j++) {
            int c = n0 + 8 * j + 2 * tg;
            float bv0 = bias[c], bv1 = bias[c + 1];
            *(uint32_t*)(dst + (uint32_t)r0 * RB + 2u * c) =
                bf16x2(acc[s][j][0] + bv0, acc[s][j][1] + bv1);
            *(uint32_t*)(dst + (uint32_t)(r0 + 8) * RB + 2u * c) =
                bf16x2(acc[s][j][2] + bv0, acc[s][j][3] + bv1);
        }
    }
}

__global__ void dango_prep(const float* __restrict__ Ws,
                           const float* __restrict__ Wq, const float* __restrict__ Wk,
                           const float* __restrict__ Wv, const float* __restrict__ Wo)
{
    int img  = blockIdx.x >> 4;
    int part = blockIdx.x & 15;
    const float* src;
    int lo = 0;
    if (img < 8) {
        int l = img >> 2, m = img & 3;
        src = (m == 0 ? Wq : m == 1 ? Wk : m == 2 ? Wv : Wo) + (size_t)l * H * H;
    } else {
        src = Ws;
        lo = (img == 9);
    }
    __nv_bfloat16* dst = g_wt[img];
#pragma unroll
    for (int i = 0; i < 4; i++) {
        int e = part * 1024 + i * 256 + threadIdx.x;
        int n = e >> 7, k = e & 127;
        float w = __ldg(src + k * H + n);
        __nv_bfloat16 v;
        if (!lo) v = __float2bfloat16(w);
        else {
            __nv_bfloat16 h = __float2bfloat16(w);
            v = __float2bfloat16(w - __bfloat162float(h));
        }
        dst[n * H + k] = v;
    }
}

__global__ __launch_bounds__(NTHREADS, 2)
void dango_mma(const float* __restrict__ X0,
               const float* __restrict__ bs_, const float* __restrict__ bq_,
               const float* __restrict__ bk_, const float* __restrict__ bv_,
               const float* __restrict__ bo_, const float* __restrict__ beta,
               const float* __restrict__ Wp, const float* __restrict__ bp,
               float* __restrict__ out)
{
    extern __shared__ unsigned char sm[];
    float*         Xs = (float*)(sm + XS_OFF);
    unsigned char* Ab = sm + AB_OFF;
    unsigned char* Qb = sm + QB_OFF;
    unsigned char* Kb = sm + KB_OFF;
    unsigned char* Vb = sm + VB_OFF;
    unsigned char* BB = sm + BB_OFF;
    float* sWp = (float*)(sm + WP_OFF);
    float* sBs = (float*)(sm + BS_OFF);
    float* sB  = (float*)(sm + B_OFF);
    float* sSc = (float*)(sm + SC_OFF);

    const int tid  = threadIdx.x;
    const int wid  = tid >> 5;
    const int lane = tid & 31;
    const int g    = lane >> 2;
    const int tg   = lane & 3;
    const int n0   = wid * 32;
    const int g0   = blockIdx.x * GPB;
    const size_t base = (size_t)g0 * SEQ * H;

    // ldmatrix lane offsets
    const uint32_t smbase = smem_u32(sm);
    const uint32_t aoff   = (uint32_t)(lane & 15) * RB + (uint32_t)(lane >> 4) * 16u;
    const uint32_t brow   = (uint32_t)(8 * ((lane >> 4) & 1) + (lane & 7));
    const uint32_t bcol   = (uint32_t)((lane >> 3) & 1) * 16u;
    const uint32_t boff0  = ((uint32_t)n0 + brow) * RB + bcol;
    const uint32_t boff1  = ((uint32_t)n0 + 16u + brow) * RB + bcol;
    const uint32_t AbA = smbase + AB_OFF, QbA = smbase + QB_OFF;
    const uint32_t KbA = smbase + KB_OFF, VbA = smbase + VB_OFF;
    const uint32_t BBA = smbase + BB_OFF;

    // ---- init: Xs, consts ----
    for (int i = 0; i < 12; i++) {
        int idx = tid + i * NTHREADS;        // 1536 float4
        int row = idx >> 5, c4 = idx & 31;
        float4 v = __ldg((const float4*)(X0 + base + (size_t)row * H + c4 * 4));
        *(float4*)(Xs + row * XSTR + c4 * 4) = v;
    }
    if (tid < H) { sWp[tid] = __ldg(Wp + tid); sBs[tid] = __ldg(bs_ + tid); }
    if (tid < TPB) sSc[tid] = __ldg(bp);
    __syncthreads();

    float acc[3][4][4];

    // ---- attention layers ----
    for (int l = 0; l < 2; l++) {
        // build/rebuild A, load biases, copy Bq
        build_A(Xs, Ab, tid);
#pragma unroll
        for (int i = 0; i < 4; i++) {
            int j = tid + i * NTHREADS;
            int m = j >> 7, c = j & 127;
            const float* p = (m == 0) ? bq_ : (m == 1) ? bk_ : (m == 2) ? bv_ : bo_;
            sB[j] = __ldg(p + l * H + c);
        }
        cp_img(BB, g_wt[l * 4 + 0], tid);
        __syncthreads();

        zero_acc(acc);
        gemm3(AbA, BBA, aoff, boff0, boff1, acc);
        epi_qkv(acc, sB + 0, Qb, n0, g, tg);
        __syncthreads();

        cp_img(BB, g_wt[l * 4 + 1], tid);
        __syncthreads();
        zero_acc(acc);
        gemm3(AbA, BBA, aoff, boff0, boff1, acc);
        epi_qkv(acc, sB + 128, Kb, n0, g, tg);
        __syncthreads();

        cp_img(BB, g_wt[l * 4 + 2], tid);
        __syncthreads();
        zero_acc(acc);
        gemm3(AbA, BBA, aoff, boff0, boff1, acc);
        epi_qkv(acc, sB + 256, Vb, n0, g, tg);
        __syncthreads();

        // copy Bo + attention (exclude-self softmax) -> Ab
        cp_img(BB, g_wt[l * 4 + 3], tid);
        if (tid < GPB * 4) {
            const int grp = tid >> 2, h = tid & 3;
            const int rb = grp * SEQ, ho = h * 32;
            const float inv = 0.17677669529663687f;   // 1/sqrt(32)
#pragma unroll
            for (int qi = 0; qi < SEQ; qi++) {
                const int k0 = (qi == 0) ? 1 : 0;
                const int k1 = (qi == 2) ? 1 : 2;
                const __nv_bfloat162* q  = (const __nv_bfloat162*)(Qb + (uint32_t)(rb + qi) * RB + 2u * ho);
                const __nv_bfloat162* ka = (const __nv_bfloat162*)(Kb + (uint32_t)(rb + k0) * RB + 2u * ho);
                const __nv_bfloat162* kb = (const __nv_bfloat162*)(Kb + (uint32_t)(rb + k1) * RB + 2u * ho);
                float s0 = 0.f, s1 = 0.f;
#pragma unroll
                for (int d = 0; d < 16; d++) {
                    float2 qv = __bfloat1622float2(q[d]);
                    float2 va = __bfloat1622float2(ka[d]);
                    float2 vb = __bfloat1622float2(kb[d]);
                    s0 += qv.x * va.x + qv.y * va.y;
                    s1 += qv.x * vb.x + qv.y * vb.y;
                }
                s0 *= inv; s1 *= inv;
                float mx = fmaxf(s0, s1);
                float e0 = expf(s0 - mx), e1 = expf(s1 - mx);
                float rr = 1.0f / (e0 + e1);
                float w0 = e0 * rr, w1 = e1 * rr;
                const __nv_bfloat162* v0 = (const __nv_bfloat162*)(Vb + (uint32_t)(rb + k0) * RB + 2u * ho);
                const __nv_bfloat162* v1 = (const __nv_bfloat162*)(Vb + (uint32_t)(rb + k1) * RB + 2u * ho);
#pragma unroll
                for (int d = 0; d < 16; d++) {
                    float2 a = __bfloat1622float2(v0[d]);
                    float2 b = __bfloat1622float2(v1[d]);
                    *(uint32_t*)(Ab + (uint32_t)(rb + qi) * RB + 2u * (ho + 2 * d)) =
                        bf16x2(w0 * a.x + w1 * b.x, w0 * a.y + w1 * b.y);
                }
            }
        }
        __syncthreads();

        // O gemm + ReZero residual into Xs
        zero_acc(acc);
        gemm3(AbA, BBA, aoff, boff0, boff1, acc);
        {
            const float betaL = __ldg(beta + l);
            const float* bo = sB + 384;
#pragma unroll
            for (int s = 0; s < 3; s++) {
                int r0 = 16 * s + g;
#pragma unroll
                for (int j = 0; j < 4; j++) {
                    int c = n0 + 8 * j + 2 * tg;
                    float bv0 = bo[c], bv1 = bo[c + 1];
                    float2* p0 = (float2*)(Xs + r0 * XSTR + c);
                    float2* p1 = (float2*)(Xs + (r0 + 8) * XSTR + c);
                    float2 x0 = *p0, x1 = *p1;
                    x0.x += betaL * (acc[s][j][0] + bv0);
                    x0.y += betaL * (acc[s][j][1] + bv1);
                    x1.x += betaL * (acc[s][j][2] + bv0);
                    x1.y += betaL * (acc[s][j][3] + bv1);
                    *p0 = x0; *p1 = x1;
                }
            }
        }
        __syncthreads();
    }

    // ---- static path: relu(X0 @ Ws + bs), hi/lo split (3 passes) ----
    // Ahi -> Kb, Alo -> Vb; Bhi first (2 passes), then Blo (1 pass)
    cp_img(BB, g_wt[8], tid);
#pragma unroll
    for (int i = 0; i < 24; i++) {
        int p = tid + i * NTHREADS;
        int row = p >> 6, cp = p & 63;
        float2 v = __ldg((const float2*)(X0 + base + (size_t)row * H + 2 * cp));
        __nv_bfloat16 h0 = __float2bfloat16(v.x), h1 = __float2bfloat16(v.y);
        float r0 = v.x - __bfloat162float(h0), r1 = v.y - __bfloat162float(h1);
        uint32_t off = (uint32_t)row * RB + (uint32_t)cp * 4u;
        __nv_bfloat162 hv = __halves2bfloat162(h0, h1);
        *(uint32_t*)(Kb + off) = *(uint32_t*)&hv;
        *(uint32_t*)(Vb + off) = bf16x2(r0, r1);
    }
    __syncthreads();

    zero_acc(acc);
    gemm3(KbA, BBA, aoff, boff0, boff1, acc);   // hi*hi
    gemm3(VbA, BBA, aoff, boff0, boff1, acc);   // lo*hi
    __syncthreads();
    cp_img(BB, g_wt[9], tid);
    __syncthreads();
    gemm3(KbA, BBA, aoff, boff0, boff1, acc);   // hi*lo

    // score epilogue
#pragma unroll
    for (int s = 0; s < 3; s++) {
        int r0 = 16 * s + g;
        float sa = 0.f, sb2 = 0.f;
#pragma unroll
        for (int j = 0; j < 4; j++) {
            int c = n0 + 8 * j + 2 * tg;
            float st, d;
            st = fmaxf(acc[s][j][0] + sBs[c], 0.f);     d = Xs[r0 * XSTR + c] - st;           sa  += d * d * sWp[c];
            st = fmaxf(acc[s][j][1] + sBs[c + 1], 0.f); d = Xs[r0 * XSTR + c + 1] - st;       sa  += d * d * sWp[c + 1];
            st = fmaxf(acc[s][j][2] + sBs[c], 0.f);     d = Xs[(r0 + 8) * XSTR + c] - st;     sb2 += d * d * sWp[c];
            st = fmaxf(acc[s][j][3] + sBs[c + 1], 0.f); d = Xs[(r0 + 8) * XSTR + c + 1] - st; sb2 += d * d * sWp[c + 1];
        }
        sa  += __shfl_xor_sync(0xffffffffu, sa, 1);
        sa  += __shfl_xor_sync(0xffffffffu, sa, 2);
        sb2 += __shfl_xor_sync(0xffffffffu, sb2, 1);
        sb2 += __shfl_xor_sync(0xffffffffu, sb2, 2);
        if (tg == 0) {
            atomicAdd(&sSc[r0], sa);
            atomicAdd(&sSc[r0 + 8], sb2);
        }
    }
    __syncthreads();

    if (tid < GPB)
        out[g0 + tid] = (sSc[tid * 3] + sSc[tid * 3 + 1] + sSc[tid * 3 + 2]) * (1.0f / 3.0f);
}

extern "C" void kernel_launch(void* const* d_in, const int* in_sizes, int n_in,
                              void* d_out, int out_size)
{
    const float* X0  = (const float*)d_in[0];
    // d_in[1] = batch (int64) — implicit: repeat(arange(G), 3)
    const float* Ws  = (const float*)d_in[2];
    const float* bs  = (const float*)d_in[3];
    const float* Wq  = (const float*)d_in[4];
    const float* bq  = (const float*)d_in[5];
    const float* Wk  = (const float*)d_in[6];
    const float* bk  = (const float*)d_in[7];
    const float* Wv  = (const float*)d_in[8];
    const float* bv  = (const float*)d_in[9];
    const float* Wo  = (const float*)d_in[10];
    const float* bo  = (const float*)d_in[11];
    const float* bet = (const float*)d_in[12];
    const float* Wp  = (const float*)d_in[13];
    const float* bp  = (const float*)d_in[14];
    float* out = (float*)d_out;

    dango_prep<<<160, 256>>>(Ws, Wq, Wk, Wv, Wo);

    cudaFuncSetAttribute(dango_mma, cudaFuncAttributeMaxDynamicSharedMemorySize, SMEM_SZ);
    dango_mma<<<GROUPS / GPB, NTHREADS, SMEM_SZ>>>(
        X0, bs, bq, bk, bv, bo, bet, Wp, bp, out);
}

// round 9
// speedup vs baseline: 8.2843x; 1.3211x over previous
#include <cuda_runtime.h>
#include <cuda_bf16.h>
#include <cstdint>

// ---------------------------------------------------------------------------
// GeneInteractionDango v8: B operands as pre-packed MMA fragments in global
// memory, LDG'd straight from L2 into registers (B never touches smem).
// A stays in smem via ldmatrix. No weight copies, QKV passes sync-free.
// GPB=16 groups (48 tokens), 128 threads, 2 blocks/SM.
// Static GEMM = 3 accumulated hi/lo bf16 passes (hi*hi + lo*hi share B frags).
// ---------------------------------------------------------------------------

#define GROUPS   131072
#define SEQ      3
#define H        128
#define GPB      16
#define TPB      48
#define NTHREADS 128

#define XSTR     132      // f32 row stride (words)
#define RB       272u     // bf16 row stride bytes

// smem byte offsets
#define XS_OFF   0        // f32 [48][132] = 25344
#define AB_OFF   25344    // bf16 [48][136] = 13056
#define QB_OFF   38400
#define KB_OFF   51456
#define VB_OFF   64512
#define WP_OFF   77568    // f32[128]
#define BS_OFF   78080    // f32[128]
#define B_OFF    78592    // f32[512] current-layer biases {q,k,v,o}
#define SC_OFF   80640    // f32[48]
#define SMEM_SZ  80832

typedef unsigned long long u64;

// B fragment store: images 0-7 = {Wq,Wk,Wv,Wo} x layer; 8 = Ws hi; 9 = Ws lo.
// frag[((img*8 + ks)*16 + j)*32 + lane] = (b0 | b1<<32) for n-tile j, k-step ks.
__device__ __align__(16) u64 g_frag[10 * 8 * 16 * 32];

__device__ __forceinline__ void mma_bf16(float* c,
                                         uint32_t a0, uint32_t a1, uint32_t a2, uint32_t a3,
                                         uint32_t b0, uint32_t b1)
{
    asm volatile(
        "mma.sync.aligned.m16n8k16.row.col.f32.bf16.bf16.f32 "
        "{%0,%1,%2,%3}, {%4,%5,%6,%7}, {%8,%9}, {%0,%1,%2,%3};"
        : "+f"(c[0]), "+f"(c[1]), "+f"(c[2]), "+f"(c[3])
        : "r"(a0), "r"(a1), "r"(a2), "r"(a3), "r"(b0), "r"(b1));
}

__device__ __forceinline__ void ldsm_x4(uint32_t& r0, uint32_t& r1, uint32_t& r2, uint32_t& r3,
                                        uint32_t addr)
{
    asm volatile("ldmatrix.sync.aligned.m8n8.x4.shared.b16 {%0,%1,%2,%3}, [%4];"
                 : "=r"(r0), "=r"(r1), "=r"(r2), "=r"(r3) : "r"(addr));
}

__device__ __forceinline__ uint32_t smem_u32(const void* p) {
    uint32_t a;
    asm("{ .reg .u64 t; cvta.to.shared.u64 t, %1; cvt.u32.u64 %0, t; }" : "=r"(a) : "l"(p));
    return a;
}

__device__ __forceinline__ uint32_t bf16x2(float a, float b) {
    __nv_bfloat162 v = __floats2bfloat162_rn(a, b);
    return *(uint32_t*)&v;
}

// [48x128] @ [128x128]: A via ldmatrix from smem, B frags via LDG from L2.
// fb = g_frag + img*4096 + wid*128 + lane  (per-warp, per-lane base)
__device__ __forceinline__ void gemm3g(uint32_t aBase, uint32_t aoff,
                                       const u64* __restrict__ fb,
                                       float acc[3][4][4])
{
    u64 cur[4];
#pragma unroll
    for (int j = 0; j < 4; j++) cur[j] = __ldg(fb + j * 32);
#pragma unroll
    for (int ks = 0; ks < 8; ks++) {
        uint32_t a[3][4];
#pragma unroll
        for (int s = 0; s < 3; s++)
            ldsm_x4(a[s][0], a[s][1], a[s][2], a[s][3],
                    aBase + (uint32_t)s * (16u * RB) + aoff + (uint32_t)ks * 32u);
        u64 nxt[4];
        if (ks < 7) {
#pragma unroll
            for (int j = 0; j < 4; j++) nxt[j] = __ldg(fb + (ks + 1) * 512 + j * 32);
        }
#pragma unroll
        for (int s = 0; s < 3; s++)
#pragma unroll
            for (int j = 0; j < 4; j++)
                mma_bf16(acc[s][j], a[s][0], a[s][1], a[s][2], a[s][3],
                         (uint32_t)cur[j], (uint32_t)(cur[j] >> 32));
        if (ks < 7) {
#pragma unroll
            for (int j = 0; j < 4; j++) cur[j] = nxt[j];
        }
    }
}

// dual-A variant: both A images multiply the SAME B fragments (static hi/lo).
__device__ __forceinline__ void gemm3g_dual(uint32_t aBase1, uint32_t aBase2, uint32_t aoff,
                                            const u64* __restrict__ fb,
                                            float acc[3][4][4])
{
#pragma unroll
    for (int ks = 0; ks < 8; ks++) {
        u64 cur[4];
#pragma unroll
        for (int j = 0; j < 4; j++) cur[j] = __ldg(fb + ks * 512 + j * 32);
        uint32_t a1[3][4], a2[3][4];
#pragma unroll
        for (int s = 0; s < 3; s++) {
            ldsm_x4(a1[s][0], a1[s][1], a1[s][2], a1[s][3],
                    aBase1 + (uint32_t)s * (16u * RB) + aoff + (uint32_t)ks * 32u);
            ldsm_x4(a2[s][0], a2[s][1], a2[s][2], a2[s][3],
                    aBase2 + (uint32_t)s * (16u * RB) + aoff + (uint32_t)ks * 32u);
        }
#pragma unroll
        for (int s = 0; s < 3; s++)
#pragma unroll
            for (int j = 0; j < 4; j++) {
                uint32_t b0 = (uint32_t)cur[j], b1 = (uint32_t)(cur[j] >> 32);
                mma_bf16(acc[s][j], a1[s][0], a1[s][1], a1[s][2], a1[s][3], b0, b1);
                mma_bf16(acc[s][j], a2[s][0], a2[s][1], a2[s][2], a2[s][3], b0, b1);
            }
    }
}

__device__ __forceinline__ void zero_acc(float acc[3][4][4]) {
#pragma unroll
    for (int s = 0; s < 3; s++)
#pragma unroll
        for (int j = 0; j < 4; j++)
#pragma unroll
            for (int e = 0; e < 4; e++) acc[s][j][e] = 0.f;
}

// bf16 A image [48][RB] from f32 Xs
__device__ __forceinline__ void build_A(const float* __restrict__ Xs,
                                        unsigned char* __restrict__ smA, int tid)
{
#pragma unroll
    for (int i = 0; i < 24; i++) {
        int p = tid + i * NTHREADS;
        int row = p >> 6, cp = p & 63;
        float2 v = *(const float2*)(Xs + row * XSTR + 2 * cp);
        *(uint32_t*)(smA + (uint32_t)row * RB + (uint32_t)cp * 4u) = bf16x2(v.x, v.y);
    }
}

__device__ __forceinline__ void epi_qkv(const float acc[3][4][4], const float* __restrict__ bias,
                                        unsigned char* __restrict__ dst, int n0, int g, int tg)
{
#pragma unroll
    for (int s = 0; s < 3; s++) {
        int r0 = 16 * s + g;
#pragma unroll
        for (int j = 0; j < 4; j++) {
            int c = n0 + 8 * j + 2 * tg;
            float bv0 = bias[c], bv1 = bias[c + 1];
            *(uint32_t*)(dst + (uint32_t)r0 * RB + 2u * c) =
                bf16x2(acc[s][j][0] + bv0, acc[s][j][1] + bv1);
            *(uint32_t*)(dst + (uint32_t)(r0 + 8) * RB + 2u * c) =
                bf16x2(acc[s][j][2] + bv0, acc[s][j][3] + bv1);
        }
    }
}

// ---------------------------------------------------------------------------
// prep: pack every weight image into mma-fragment order.
// frag for (img, ks, j, lane): n = 8j + (lane>>2), k0 = 16ks + 2(lane&3)
//   b0 = {W[k0][n], W[k0+1][n]}, b1 = {W[k0+8][n], W[k0+9][n]}
// ---------------------------------------------------------------------------
__global__ void dango_prep(const float* __restrict__ Ws,
                           const float* __restrict__ Wq, const float* __restrict__ Wk,
                           const float* __restrict__ Wv, const float* __restrict__ Wo)
{
    int t = blockIdx.x * 256 + threadIdx.x;      // 0..40959
    int img  = t >> 12;
    int r    = t & 4095;
    int ks   = r >> 9;
    int j    = (r >> 5) & 15;
    int lane = r & 31;
    int g = lane >> 2, tg = lane & 3;
    int n  = 8 * j + g;
    int k0 = 16 * ks + 2 * tg;

    const float* src;
    int lo = 0;
    if (img < 8) {
        int l = img >> 2, m = img & 3;
        src = (m == 0 ? Wq : m == 1 ? Wk : m == 2 ? Wv : Wo) + (size_t)l * H * H;
    } else {
        src = Ws;
        lo = (img == 9);
    }

    float w[4];
    w[0] = __ldg(src + (k0)     * H + n);
    w[1] = __ldg(src + (k0 + 1) * H + n);
    w[2] = __ldg(src + (k0 + 8) * H + n);
    w[3] = __ldg(src + (k0 + 9) * H + n);

    __nv_bfloat16 v[4];
#pragma unroll
    for (int i = 0; i < 4; i++) {
        if (!lo) v[i] = __float2bfloat16(w[i]);
        else {
            __nv_bfloat16 h = __float2bfloat16(w[i]);
            v[i] = __float2bfloat16(w[i] - __bfloat162float(h));
        }
    }
    uint32_t b0, b1;
    { __nv_bfloat162 p = __halves2bfloat162(v[0], v[1]); b0 = *(uint32_t*)&p; }
    { __nv_bfloat162 p = __halves2bfloat162(v[2], v[3]); b1 = *(uint32_t*)&p; }
    g_frag[t] = (u64)b0 | ((u64)b1 << 32);
}

__global__ __launch_bounds__(NTHREADS, 2)
void dango_mma(const float* __restrict__ X0,
               const float* __restrict__ bs_, const float* __restrict__ bq_,
               const float* __restrict__ bk_, const float* __restrict__ bv_,
               const float* __restrict__ bo_, const float* __restrict__ beta,
               const float* __restrict__ Wp, const float* __restrict__ bp,
               float* __restrict__ out)
{
    extern __shared__ unsigned char sm[];
    float*         Xs = (float*)(sm + XS_OFF);
    unsigned char* Ab = sm + AB_OFF;
    unsigned char* Qb = sm + QB_OFF;
    unsigned char* Kb = sm + KB_OFF;
    unsigned char* Vb = sm + VB_OFF;
    float* sWp = (float*)(sm + WP_OFF);
    float* sBs = (float*)(sm + BS_OFF);
    float* sB  = (float*)(sm + B_OFF);
    float* sSc = (float*)(sm + SC_OFF);

    const int tid  = threadIdx.x;
    const int wid  = tid >> 5;
    const int lane = tid & 31;
    const int g    = lane >> 2;
    const int tg   = lane & 3;
    const int n0   = wid * 32;
    const int g0   = blockIdx.x * GPB;
    const size_t base = (size_t)g0 * SEQ * H;

    const uint32_t smbase = smem_u32(sm);
    const uint32_t aoff   = (uint32_t)(lane & 15) * RB + (uint32_t)(lane >> 4) * 16u;
    const uint32_t AbA = smbase + AB_OFF;
    const uint32_t KbA = smbase + KB_OFF, VbA = smbase + VB_OFF;
    const u64* fwarp = g_frag + wid * 128 + lane;   // + img*4096 + ks*512 + j*32

    // ---- init: Xs, consts ----
    for (int i = 0; i < 12; i++) {
        int idx = tid + i * NTHREADS;
        int row = idx >> 5, c4 = idx & 31;
        float4 v = __ldg((const float4*)(X0 + base + (size_t)row * H + c4 * 4));
        *(float4*)(Xs + row * XSTR + c4 * 4) = v;
    }
    if (tid < H) { sWp[tid] = __ldg(Wp + tid); sBs[tid] = __ldg(bs_ + tid); }
    if (tid < TPB) sSc[tid] = __ldg(bp);
    __syncthreads();

    float acc[3][4][4];

    // ---- attention layers ----
    for (int l = 0; l < 2; l++) {
        build_A(Xs, Ab, tid);
#pragma unroll
        for (int i = 0; i < 4; i++) {
            int j = tid + i * NTHREADS;
            int m = j >> 7, c = j & 127;
            const float* p = (m == 0) ? bq_ : (m == 1) ? bk_ : (m == 2) ? bv_ : bo_;
            sB[j] = __ldg(p + l * H + c);
        }
        __syncthreads();

        // Q, K, V back-to-back, no syncs (each writes a private buffer)
        zero_acc(acc);
        gemm3g(AbA, aoff, fwarp + (l * 4 + 0) * 4096, acc);
        epi_qkv(acc, sB + 0, Qb, n0, g, tg);

        zero_acc(acc);
        gemm3g(AbA, aoff, fwarp + (l * 4 + 1) * 4096, acc);
        epi_qkv(acc, sB + 128, Kb, n0, g, tg);

        zero_acc(acc);
        gemm3g(AbA, aoff, fwarp + (l * 4 + 2) * 4096, acc);
        epi_qkv(acc, sB + 256, Vb, n0, g, tg);
        __syncthreads();

        // attention (exclude-self softmax) -> Ab
        if (tid < GPB * 4) {
            const int grp = tid >> 2, h = tid & 3;
            const int rb = grp * SEQ, ho = h * 32;
            const float inv = 0.17677669529663687f;   // 1/sqrt(32)
#pragma unroll
            for (int qi = 0; qi < SEQ; qi++) {
                const int k0 = (qi == 0) ? 1 : 0;
                const int k1 = (qi == 2) ? 1 : 2;
                const __nv_bfloat162* q  = (const __nv_bfloat162*)(Qb + (uint32_t)(rb + qi) * RB + 2u * ho);
                const __nv_bfloat162* ka = (const __nv_bfloat162*)(Kb + (uint32_t)(rb + k0) * RB + 2u * ho);
                const __nv_bfloat162* kb = (const __nv_bfloat162*)(Kb + (uint32_t)(rb + k1) * RB + 2u * ho);
                float s0 = 0.f, s1 = 0.f;
#pragma unroll
                for (int d = 0; d < 16; d++) {
                    float2 qv = __bfloat1622float2(q[d]);
                    float2 va = __bfloat1622float2(ka[d]);
                    float2 vb = __bfloat1622float2(kb[d]);
                    s0 += qv.x * va.x + qv.y * va.y;
                    s1 += qv.x * vb.x + qv.y * vb.y;
                }
                s0 *= inv; s1 *= inv;
                float mx = fmaxf(s0, s1);
                float e0 = expf(s0 - mx), e1 = expf(s1 - mx);
                float rr = 1.0f / (e0 + e1);
                float w0 = e0 * rr, w1 = e1 * rr;
                const __nv_bfloat162* v0 = (const __nv_bfloat162*)(Vb + (uint32_t)(rb + k0) * RB + 2u * ho);
                const __nv_bfloat162* v1 = (const __nv_bfloat162*)(Vb + (uint32_t)(rb + k1) * RB + 2u * ho);
#pragma unroll
                for (int d = 0; d < 16; d++) {
                    float2 a = __bfloat1622float2(v0[d]);
                    float2 b = __bfloat1622float2(v1[d]);
                    *(uint32_t*)(Ab + (uint32_t)(rb + qi) * RB + 2u * (ho + 2 * d)) =
                        bf16x2(w0 * a.x + w1 * b.x, w0 * a.y + w1 * b.y);
                }
            }
        }
        __syncthreads();

        // O gemm + ReZero residual into Xs
        zero_acc(acc);
        gemm3g(AbA, aoff, fwarp + (l * 4 + 3) * 4096, acc);
        {
            const float betaL = __ldg(beta + l);
            const float* bo = sB + 384;
#pragma unroll
            for (int s = 0; s < 3; s++) {
                int r0 = 16 * s + g;
#pragma unroll
                for (int j = 0; j < 4; j++) {
                    int c = n0 + 8 * j + 2 * tg;
                    float bv0 = bo[c], bv1 = bo[c + 1];
                    float2* p0 = (float2*)(Xs + r0 * XSTR + c);
                    float2* p1 = (float2*)(Xs + (r0 + 8) * XSTR + c);
                    float2 x0 = *p0, x1 = *p1;
                    x0.x += betaL * (acc[s][j][0] + bv0);
                    x0.y += betaL * (acc[s][j][1] + bv1);
                    x1.x += betaL * (acc[s][j][2] + bv0);
                    x1.y += betaL * (acc[s][j][3] + bv1);
                    *p0 = x0; *p1 = x1;
                }
            }
        }
        __syncthreads();
    }

    // ---- static path: relu(X0 @ Ws + bs), hi/lo split ----
    // Ahi -> Kb, Alo -> Vb (free after attention of layer 1)
#pragma unroll
    for (int i = 0; i < 24; i++) {
        int p = tid + i * NTHREADS;
        int row = p >> 6, cp = p & 63;
        float2 v = __ldg((const float2*)(X0 + base + (size_t)row * H + 2 * cp));
        __nv_bfloat16 h0 = __float2bfloat16(v.x), h1 = __float2bfloat16(v.y);
        float r0 = v.x - __bfloat162float(h0), r1 = v.y - __bfloat162float(h1);
        uint32_t off = (uint32_t)row * RB + (uint32_t)cp * 4u;
        __nv_bfloat162 hv = __halves2bfloat162(h0, h1);
        *(uint32_t*)(Kb + off) = *(uint32_t*)&hv;
        *(uint32_t*)(Vb + off) = bf16x2(r0, r1);
    }
    __syncthreads();

    zero_acc(acc);
    gemm3g_dual(KbA, VbA, aoff, fwarp + 8 * 4096, acc);   // hi*hi + lo*hi
    gemm3g(KbA, aoff, fwarp + 9 * 4096, acc);             // hi*lo

    // score epilogue
#pragma unroll
    for (int s = 0; s < 3; s++) {
        int r0 = 16 * s + g;
        float sa = 0.f, sb2 = 0.f;
#pragma unroll
        for (int j = 0; j < 4; j++) {
            int c = n0 + 8 * j + 2 * tg;
            float st, d;
            st = fmaxf(acc[s][j][0] + sBs[c], 0.f);     d = Xs[r0 * XSTR + c] - st;           sa  += d * d * sWp[c];
            st = fmaxf(acc[s][j][1] + sBs[c + 1], 0.f); d = Xs[r0 * XSTR + c + 1] - st;       sa  += d * d * sWp[c + 1];
            st = fmaxf(acc[s][j][2] + sBs[c], 0.f);     d = Xs[(r0 + 8) * XSTR + c] - st;     sb2 += d * d * sWp[c];
            st = fmaxf(acc[s][j][3] + sBs[c + 1], 0.f); d = Xs[(r0 + 8) * XSTR + c + 1] - st; sb2 += d * d * sWp[c + 1];
        }
        sa  += __shfl_xor_sync(0xffffffffu, sa, 1);
        sa  += __shfl_xor_sync(0xffffffffu, sa, 2);
        sb2 += __shfl_xor_sync(0xffffffffu, sb2, 1);
        sb2 += __shfl_xor_sync(0xffffffffu, sb2, 2);
        if (tg == 0) {
            atomicAdd(&sSc[r0], sa);
            atomicAdd(&sSc[r0 + 8], sb2);
        }
    }
    __syncthreads();

    if (tid < GPB)
        out[g0 + tid] = (sSc[tid * 3] + sSc[tid * 3 + 1] + sSc[tid * 3 + 2]) * (1.0f / 3.0f);
}

extern "C" void kernel_launch(void* const* d_in, const int* in_sizes, int n_in,
                              void* d_out, int out_size)
{
    const float* X0  = (const float*)d_in[0];
    // d_in[1] = batch (int64) — implicit: repeat(arange(G), 3)
    const float* Ws  = (const float*)d_in[2];
    const float* bs  = (const float*)d_in[3];
    const float* Wq  = (const float*)d_in[4];
    const float* bq  = (const float*)d_in[5];
    const float* Wk  = (const float*)d_in[6];
    const float* bk  = (const float*)d_in[7];
    const float* Wv  = (const float*)d_in[8];
    const float* bv  = (const float*)d_in[9];
    const float* Wo  = (const float*)d_in[10];
    const float* bo  = (const float*)d_in[11];
    const float* bet = (const float*)d_in[12];
    const float* Wp  = (const float*)d_in[13];
    const float* bp  = (const float*)d_in[14];
    float* out = (float*)d_out;

    dango_prep<<<160, 256>>>(Ws, Wq, Wk, Wv, Wo);

    cudaFuncSetAttribute(dango_mma, cudaFuncAttributeMaxDynamicSharedMemorySize, SMEM_SZ);
    dango_mma<<<GROUPS / GPB, NTHREADS, SMEM_SZ>>>(
        X0, bs, bq, bk, bv, bo, bet, Wp, bp, out);
}

// round 10
// speedup vs baseline: 8.2895x; 1.0006x over previous
#include <cuda_runtime.h>
#include <cuda_bf16.h>
#include <cstdint>

// ---------------------------------------------------------------------------
// GeneInteractionDango v9: algebraic V*O fusion + fused Q/K pass.
//   P(xWv+bv)Wo == x(WvWo) + bvWo  (P commutes with right-multiplication),
//   so the O GEMM disappears; attention applies the ReZero residual directly.
// Q and K share one A-ldmatrix pass (two B streams, two accumulators).
// B operands pre-packed as mma fragments in global (LDG from L2, no smem).
// Static relu(X0@Ws+bs) via 3 accumulated hi/lo bf16 passes.
// GPB=16 groups (48 tokens), 128 threads, 2 blocks/SM.
// ---------------------------------------------------------------------------

#define GROUPS   131072
#define SEQ      3
#define H        128
#define GPB      16
#define TPB      48
#define NTHREADS 128

#define XSTR     132      // f32 row stride (words)
#define RB       272u     // bf16 row stride bytes

// smem byte offsets
#define XS_OFF   0        // f32 [48][132] = 25344
#define AB_OFF   25344    // bf16 [48][136] = 13056
#define QB_OFF   38400
#define KB_OFF   51456
#define VB_OFF   64512
#define WP_OFF   77568    // f32[128]
#define BS_OFF   78080    // f32[128]
#define B_OFF    78592    // f32[512] biases {bq, bk, bvo, bo}
#define SC_OFF   80640    // f32[48]
#define SMEM_SZ  80832

typedef unsigned long long u64;

// frag images: 0:Wq0 1:Wk0 2:Wvo0 3:Wq1 4:Wk1 5:Wvo1 6:Ws_hi 7:Ws_lo
// frag[((img*8 + ks)*16 + j)*32 + lane] = (b0 | b1<<32)
__device__ __align__(16) u64   g_frag[8 * 8 * 16 * 32];
__device__ __align__(16) float g_wvo[2][H * H];     // Wv@Wo, [k][n]
__device__ __align__(16) float g_bvo[2][H];         // bv@Wo

__device__ __forceinline__ void mma_bf16(float* c,
                                         uint32_t a0, uint32_t a1, uint32_t a2, uint32_t a3,
                                         uint32_t b0, uint32_t b1)
{
    asm volatile(
        "mma.sync.aligned.m16n8k16.row.col.f32.bf16.bf16.f32 "
        "{%0,%1,%2,%3}, {%4,%5,%6,%7}, {%8,%9}, {%0,%1,%2,%3};"
        : "+f"(c[0]), "+f"(c[1]), "+f"(c[2]), "+f"(c[3])
        : "r"(a0), "r"(a1), "r"(a2), "r"(a3), "r"(b0), "r"(b1));
}

__device__ __forceinline__ void ldsm_x4(uint32_t& r0, uint32_t& r1, uint32_t& r2, uint32_t& r3,
                                        uint32_t addr)
{
    asm volatile("ldmatrix.sync.aligned.m8n8.x4.shared.b16 {%0,%1,%2,%3}, [%4];"
                 : "=r"(r0), "=r"(r1), "=r"(r2), "=r"(r3) : "r"(addr));
}

__device__ __forceinline__ uint32_t smem_u32(const void* p) {
    uint32_t a;
    asm("{ .reg .u64 t; cvta.to.shared.u64 t, %1; cvt.u32.u64 %0, t; }" : "=r"(a) : "l"(p));
    return a;
}

__device__ __forceinline__ uint32_t bf16x2(float a, float b) {
    __nv_bfloat162 v = __floats2bfloat162_rn(a, b);
    return *(uint32_t*)&v;
}

// single-B GEMM pass: [48x128]@[128x128], A via ldmatrix, B frags via LDG
__device__ __forceinline__ void gemm3g(uint32_t aBase, uint32_t aoff,
                                       const u64* __restrict__ fb,
                                       float acc[3][4][4])
{
    u64 cur[4];
#pragma unroll
    for (int j = 0; j < 4; j++) cur[j] = __ldg(fb + j * 32);
#pragma unroll
    for (int ks = 0; ks < 8; ks++) {
        uint32_t a[3][4];
#pragma unroll
        for (int s = 0; s < 3; s++)
            ldsm_x4(a[s][0], a[s][1], a[s][2], a[s][3],
                    aBase + (uint32_t)s * (16u * RB) + aoff + (uint32_t)ks * 32u);
        u64 nxt[4];
        if (ks < 7) {
#pragma unroll
            for (int j = 0; j < 4; j++) nxt[j] = __ldg(fb + (ks + 1) * 512 + j * 32);
        }
#pragma unroll
        for (int s = 0; s < 3; s++)
#pragma unroll
            for (int j = 0; j < 4; j++)
                mma_bf16(acc[s][j], a[s][0], a[s][1], a[s][2], a[s][3],
                         (uint32_t)cur[j], (uint32_t)(cur[j] >> 32));
        if (ks < 7) {
#pragma unroll
            for (int j = 0; j < 4; j++) cur[j] = nxt[j];
        }
    }
}

// fused two-B GEMM pass: one A-ldmatrix stream feeds two accumulator sets
__device__ __forceinline__ void gemm3g2(uint32_t aBase, uint32_t aoff,
                                        const u64* __restrict__ fb1,
                                        const u64* __restrict__ fb2,
                                        float acc1[3][4][4], float acc2[3][4][4])
{
    u64 c1[4], c2[4];
#pragma unroll
    for (int j = 0; j < 4; j++) { c1[j] = __ldg(fb1 + j * 32); c2[j] = __ldg(fb2 + j * 32); }
#pragma unroll
    for (int ks = 0; ks < 8; ks++) {
        uint32_t a[3][4];
#pragma unroll
        for (int s = 0; s < 3; s++)
            ldsm_x4(a[s][0], a[s][1], a[s][2], a[s][3],
                    aBase + (uint32_t)s * (16u * RB) + aoff + (uint32_t)ks * 32u);
        u64 n1[4], n2[4];
        if (ks < 7) {
#pragma unroll
            for (int j = 0; j < 4; j++) {
                n1[j] = __ldg(fb1 + (ks + 1) * 512 + j * 32);
                n2[j] = __ldg(fb2 + (ks + 1) * 512 + j * 32);
            }
        }
#pragma unroll
        for (int s = 0; s < 3; s++)
#pragma unroll
            for (int j = 0; j < 4; j++) {
                mma_bf16(acc1[s][j], a[s][0], a[s][1], a[s][2], a[s][3],
                         (uint32_t)c1[j], (uint32_t)(c1[j] >> 32));
                mma_bf16(acc2[s][j], a[s][0], a[s][1], a[s][2], a[s][3],
                         (uint32_t)c2[j], (uint32_t)(c2[j] >> 32));
            }
        if (ks < 7) {
#pragma unroll
            for (int j = 0; j < 4; j++) { c1[j] = n1[j]; c2[j] = n2[j]; }
        }
    }
}

// dual-A, shared-B (static hi/lo)
__device__ __forceinline__ void gemm3g_dual(uint32_t aBase1, uint32_t aBase2, uint32_t aoff,
                                            const u64* __restrict__ fb,
                                            float acc[3][4][4])
{
#pragma unroll
    for (int ks = 0; ks < 8; ks++) {
        u64 cur[4];
#pragma unroll
        for (int j = 0; j < 4; j++) cur[j] = __ldg(fb + ks * 512 + j * 32);
        uint32_t a1[3][4], a2[3][4];
#pragma unroll
        for (int s = 0; s < 3; s++) {
            ldsm_x4(a1[s][0], a1[s][1], a1[s][2], a1[s][3],
                    aBase1 + (uint32_t)s * (16u * RB) + aoff + (uint32_t)ks * 32u);
            ldsm_x4(a2[s][0], a2[s][1], a2[s][2], a2[s][3],
                    aBase2 + (uint32_t)s * (16u * RB) + aoff + (uint32_t)ks * 32u);
        }
#pragma unroll
        for (int s = 0; s < 3; s++)
#pragma unroll
            for (int j = 0; j < 4; j++) {
                uint32_t b0 = (uint32_t)cur[j], b1 = (uint32_t)(cur[j] >> 32);
                mma_bf16(acc[s][j], a1[s][0], a1[s][1], a1[s][2], a1[s][3], b0, b1);
                mma_bf16(acc[s][j], a2[s][0], a2[s][1], a2[s][2], a2[s][3], b0, b1);
            }
    }
}

__device__ __forceinline__ void zero_acc(float acc[3][4][4]) {
#pragma unroll
    for (int s = 0; s < 3; s++)
#pragma unroll
        for (int j = 0; j < 4; j++)
#pragma unroll
            for (int e = 0; e < 4; e++) acc[s][j][e] = 0.f;
}

__device__ __forceinline__ void build_A(const float* __restrict__ Xs,
                                        unsigned char* __restrict__ smA, int tid)
{
#pragma unroll
    for (int i = 0; i < 24; i++) {
        int p = tid + i * NTHREADS;
        int row = p >> 6, cp = p & 63;
        float2 v = *(const float2*)(Xs + row * XSTR + 2 * cp);
        *(uint32_t*)(smA + (uint32_t)row * RB + (uint32_t)cp * 4u) = bf16x2(v.x, v.y);
    }
}

__device__ __forceinline__ void epi_qkv(const float acc[3][4][4], const float* __restrict__ bias,
                                        unsigned char* __restrict__ dst, int n0, int g, int tg)
{
#pragma unroll
    for (int s = 0; s < 3; s++) {
        int r0 = 16 * s + g;
#pragma unroll
        for (int j = 0; j < 4; j++) {
            int c = n0 + 8 * j + 2 * tg;
            float bv0 = bias[c], bv1 = bias[c + 1];
            *(uint32_t*)(dst + (uint32_t)r0 * RB + 2u * c) =
                bf16x2(acc[s][j][0] + bv0, acc[s][j][1] + bv1);
            *(uint32_t*)(dst + (uint32_t)(r0 + 8) * RB + 2u * c) =
                bf16x2(acc[s][j][2] + bv0, acc[s][j][3] + bv1);
        }
    }
}

// ---------------------------------------------------------------------------
// prep 1: Wvo = Wv@Wo (fp32), bvo = bv@Wo
// ---------------------------------------------------------------------------
__global__ void dango_prep_vo(const float* __restrict__ Wv, const float* __restrict__ Wo,
                              const float* __restrict__ bv)
{
    int b = blockIdx.x;
    int n = threadIdx.x;
    if (b < 256) {
        int l = b >> 7, k = b & 127;
        const float* wv = Wv + (size_t)l * H * H + (size_t)k * H;
        const float* wo = Wo + (size_t)l * H * H;
        float s = 0.f;
#pragma unroll 8
        for (int m = 0; m < H; m++) s += __ldg(wv + m) * __ldg(wo + m * H + n);
        g_wvo[l][k * H + n] = s;
    } else {
        int l = b - 256;
        const float* wo = Wo + (size_t)l * H * H;
        const float* bvp = bv + l * H;
        float s = 0.f;
#pragma unroll 8
        for (int k = 0; k < H; k++) s += __ldg(bvp + k) * __ldg(wo + k * H + n);
        g_bvo[l][n] = s;
    }
}

// ---------------------------------------------------------------------------
// prep 2: pack 8 weight images into mma-fragment order.
// (img, ks, j, lane): n = 8j + (lane>>2), k0 = 16ks + 2(lane&3)
// ---------------------------------------------------------------------------
__global__ void dango_prep_pack(const float* __restrict__ Ws,
                                const float* __restrict__ Wq, const float* __restrict__ Wk)
{
    int t = blockIdx.x * 256 + threadIdx.x;      // 0..32767
    int img  = t >> 12;
    int r    = t & 4095;
    int ks   = r >> 9;
    int j    = (r >> 5) & 15;
    int lane = r & 31;
    int n  = 8 * j + (lane >> 2);
    int k0 = 16 * ks + 2 * (lane & 3);

    const float* src;
    int lo = 0;
    if (img < 6) {
        int l = img / 3, m = img % 3;
        src = (m == 0) ? Wq + (size_t)l * H * H
            : (m == 1) ? Wk + (size_t)l * H * H
                       : g_wvo[l];
    } else {
        src = Ws;
        lo = (img == 7);
    }

    float w[4];
    w[0] = __ldg(src + (k0)     * H + n);
    w[1] = __ldg(src + (k0 + 1) * H + n);
    w[2] = __ldg(src + (k0 + 8) * H + n);
    w[3] = __ldg(src + (k0 + 9) * H + n);

    __nv_bfloat16 v[4];
#pragma unroll
    for (int i = 0; i < 4; i++) {
        if (!lo) v[i] = __float2bfloat16(w[i]);
        else {
            __nv_bfloat16 h = __float2bfloat16(w[i]);
            v[i] = __float2bfloat16(w[i] - __bfloat162float(h));
        }
    }
    uint32_t b0, b1;
    { __nv_bfloat162 p = __halves2bfloat162(v[0], v[1]); b0 = *(uint32_t*)&p; }
    { __nv_bfloat162 p = __halves2bfloat162(v[2], v[3]); b1 = *(uint32_t*)&p; }
    g_frag[t] = (u64)b0 | ((u64)b1 << 32);
}

__global__ __launch_bounds__(NTHREADS, 2)
void dango_mma(const float* __restrict__ X0,
               const float* __restrict__ bs_, const float* __restrict__ bq_,
               const float* __restrict__ bk_, const float* __restrict__ bo_,
               const float* __restrict__ beta,
               const float* __restrict__ Wp, const float* __restrict__ bp,
               float* __restrict__ out)
{
    extern __shared__ unsigned char sm[];
    float*         Xs = (float*)(sm + XS_OFF);
    unsigned char* Ab = sm + AB_OFF;
    unsigned char* Qb = sm + QB_OFF;
    unsigned char* Kb = sm + KB_OFF;
    unsigned char* Vb = sm + VB_OFF;
    float* sWp = (float*)(sm + WP_OFF);
    float* sBs = (float*)(sm + BS_OFF);
    float* sB  = (float*)(sm + B_OFF);
    float* sSc = (float*)(sm + SC_OFF);

    const int tid  = threadIdx.x;
    const int wid  = tid >> 5;
    const int lane = tid & 31;
    const int g    = lane >> 2;
    const int tg   = lane & 3;
    const int n0   = wid * 32;
    const int g0   = blockIdx.x * GPB;
    const size_t base = (size_t)g0 * SEQ * H;

    const uint32_t smbase = smem_u32(sm);
    const uint32_t aoff   = (uint32_t)(lane & 15) * RB + (uint32_t)(lane >> 4) * 16u;
    const uint32_t AbA = smbase + AB_OFF;
    const uint32_t KbA = smbase + KB_OFF, VbA = smbase + VB_OFF;
    const u64* fwarp = g_frag + wid * 128 + lane;   // + img*4096 + ks*512 + j*32

    // ---- init ----
    for (int i = 0; i < 12; i++) {
        int idx = tid + i * NTHREADS;
        int row = idx >> 5, c4 = idx & 31;
        float4 v = __ldg((const float4*)(X0 + base + (size_t)row * H + c4 * 4));
        *(float4*)(Xs + row * XSTR + c4 * 4) = v;
    }
    if (tid < H) { sWp[tid] = __ldg(Wp + tid); sBs[tid] = __ldg(bs_ + tid); }
    if (tid < TPB) sSc[tid] = __ldg(bp);
    __syncthreads();

    float accQ[3][4][4], accK[3][4][4];

    // ---- attention layers ----
    for (int l = 0; l < 2; l++) {
        build_A(Xs, Ab, tid);
#pragma unroll
        for (int i = 0; i < 4; i++) {
            int j = tid + i * NTHREADS;
            int m = j >> 7, c = j & 127;
            float v;
            if      (m == 0) v = __ldg(bq_ + l * H + c);
            else if (m == 1) v = __ldg(bk_ + l * H + c);
            else if (m == 2) v = g_bvo[l][c];
            else             v = __ldg(bo_ + l * H + c);
            sB[j] = v;
        }
        __syncthreads();

        // fused Q+K pass (one A stream), then VO pass — all sync-free
        zero_acc(accQ); zero_acc(accK);
        gemm3g2(AbA, aoff, fwarp + (l * 3 + 0) * 4096, fwarp + (l * 3 + 1) * 4096, accQ, accK);
        epi_qkv(accQ, sB + 0,   Qb, n0, g, tg);
        epi_qkv(accK, sB + 128, Kb, n0, g, tg);

        zero_acc(accQ);
        gemm3g(AbA, aoff, fwarp + (l * 3 + 2) * 4096, accQ);
        epi_qkv(accQ, sB + 256, Vb, n0, g, tg);
        __syncthreads();

        // attention + fused ReZero residual: Xs += beta * (P*VO + bo)
        if (tid < 96) {
            const int grp = tid / 6;
            const int rr  = tid % 6;
            const int qi  = rr >> 1;
            const int hp  = rr & 1;
            const int rb  = grp * SEQ;
            const int row = rb + qi;
            const int k0  = (qi == 0) ? 1 : 0;
            const int k1  = (qi == 2) ? 1 : 2;
            const float inv = 0.17677669529663687f;   // 1/sqrt(32)
            const float betaL = __ldg(beta + l);
            const float* bo = sB + 384;
#pragma unroll
            for (int hh = 0; hh < 2; hh++) {
                const int ho = (2 * hp + hh) * 32;
                const __nv_bfloat162* q  = (const __nv_bfloat162*)(Qb + (uint32_t)row * RB + 2u * ho);
                const __nv_bfloat162* ka = (const __nv_bfloat162*)(Kb + (uint32_t)(rb + k0) * RB + 2u * ho);
                const __nv_bfloat162* kb = (const __nv_bfloat162*)(Kb + (uint32_t)(rb + k1) * RB + 2u * ho);
                float s0 = 0.f, s1 = 0.f;
#pragma unroll
                for (int d = 0; d < 16; d++) {
                    float2 qv = __bfloat1622float2(q[d]);
                    float2 va = __bfloat1622float2(ka[d]);
                    float2 vb = __bfloat1622float2(kb[d]);
                    s0 += qv.x * va.x + qv.y * va.y;
                    s1 += qv.x * vb.x + qv.y * vb.y;
                }
                s0 *= inv; s1 *= inv;
                float mx = fmaxf(s0, s1);
                float e0 = expf(s0 - mx), e1 = expf(s1 - mx);
                float rcp = 1.0f / (e0 + e1);
                float w0 = e0 * rcp, w1 = e1 * rcp;
                const __nv_bfloat162* v0 = (const __nv_bfloat162*)(Vb + (uint32_t)(rb + k0) * RB + 2u * ho);
                const __nv_bfloat162* v1 = (const __nv_bfloat162*)(Vb + (uint32_t)(rb + k1) * RB + 2u * ho);
                float2* xp = (float2*)(Xs + row * XSTR + ho);
#pragma unroll
                for (int d = 0; d < 16; d++) {
                    float2 a = __bfloat1622float2(v0[d]);
                    float2 b = __bfloat1622float2(v1[d]);
                    float2 x = xp[d];
                    x.x += betaL * (w0 * a.x + w1 * b.x + bo[ho + 2 * d]);
                    x.y += betaL * (w0 * a.y + w1 * b.y + bo[ho + 2 * d + 1]);
                    xp[d] = x;
                }
            }
        }
        __syncthreads();
    }

    // ---- static path: relu(X0 @ Ws + bs), hi/lo split ----
#pragma unroll
    for (int i = 0; i < 24; i++) {
        int p = tid + i * NTHREADS;
        int row = p >> 6, cp = p & 63;
        float2 v = __ldg((const float2*)(X0 + base + (size_t)row * H + 2 * cp));
        __nv_bfloat16 h0 = __float2bfloat16(v.x), h1 = __float2bfloat16(v.y);
        float r0 = v.x - __bfloat162float(h0), r1 = v.y - __bfloat162float(h1);
        uint32_t off = (uint32_t)row * RB + (uint32_t)cp * 4u;
        __nv_bfloat162 hv = __halves2bfloat162(h0, h1);
        *(uint32_t*)(Kb + off) = *(uint32_t*)&hv;       // A_hi
        *(uint32_t*)(Vb + off) = bf16x2(r0, r1);        // A_lo
    }
    __syncthreads();

    zero_acc(accQ);
    gemm3g_dual(KbA, VbA, aoff, fwarp + 6 * 4096, accQ);   // hi*hi + lo*hi
    gemm3g(KbA, aoff, fwarp + 7 * 4096, accQ);             // hi*lo

    // score epilogue
#pragma unroll
    for (int s = 0; s < 3; s++) {
        int r0 = 16 * s + g;
        float sa = 0.f, sb2 = 0.f;
#pragma unroll
        for (int j = 0; j < 4; j++) {
            int c = n0 + 8 * j + 2 * tg;
            float st, d;
            st = fmaxf(accQ[s][j][0] + sBs[c], 0.f);     d = Xs[r0 * XSTR + c] - st;           sa  += d * d * sWp[c];
            st = fmaxf(accQ[s][j][1] + sBs[c + 1], 0.f); d = Xs[r0 * XSTR + c + 1] - st;       sa  += d * d * sWp[c + 1];
            st = fmaxf(accQ[s][j][2] + sBs[c], 0.f);     d = Xs[(r0 + 8) * XSTR + c] - st;     sb2 += d * d * sWp[c];
            st = fmaxf(accQ[s][j][3] + sBs[c + 1], 0.f); d = Xs[(r0 + 8) * XSTR + c + 1] - st; sb2 += d * d * sWp[c + 1];
        }
        sa  += __shfl_xor_sync(0xffffffffu, sa, 1);
        sa  += __shfl_xor_sync(0xffffffffu, sa, 2);
        sb2 += __shfl_xor_sync(0xffffffffu, sb2, 1);
        sb2 += __shfl_xor_sync(0xffffffffu, sb2, 2);
        if (tg == 0) {
            atomicAdd(&sSc[r0], sa);
            atomicAdd(&sSc[r0 + 8], sb2);
        }
    }
    __syncthreads();

    if (tid < GPB)
        out[g0 + tid] = (sSc[tid * 3] + sSc[tid * 3 + 1] + sSc[tid * 3 + 2]) * (1.0f / 3.0f);
}

extern "C" void kernel_launch(void* const* d_in, const int* in_sizes, int n_in,
                              void* d_out, int out_size)
{
    const float* X0  = (const float*)d_in[0];
    // d_in[1] = batch (int64) — implicit: repeat(arange(G), 3)
    const float* Ws  = (const float*)d_in[2];
    const float* bs  = (const float*)d_in[3];
    const float* Wq  = (const float*)d_in[4];
    const float* bq  = (const float*)d_in[5];
    const float* Wk  = (const float*)d_in[6];
    const float* bk  = (const float*)d_in[7];
    const float* Wv  = (const float*)d_in[8];
    const float* bv  = (const float*)d_in[9];
    const float* Wo  = (const float*)d_in[10];
    const float* bo  = (const float*)d_in[11];
    const float* bet = (const float*)d_in[12];
    const float* Wp  = (const float*)d_in[13];
    const float* bp  = (const float*)d_in[14];
    float* out = (float*)d_out;

    dango_prep_vo<<<258, 128>>>(Wv, Wo, bv);
    dango_prep_pack<<<128, 256>>>(Ws, Wq, Wk);

    cudaFuncSetAttribute(dango_mma, cudaFuncAttributeMaxDynamicSharedMemorySize, SMEM_SZ);
    dango_mma<<<GROUPS / GPB, NTHREADS, SMEM_SZ>>>(
        X0, bs, bq, bk, bo, bet, Wp, bp, out);
}